// round 7
// baseline (speedup 1.0000x reference)
#include <cuda_runtime.h>
#include <cuda_bf16.h>
#include <cstdint>
#include <math.h>

// Problem constants
#define BATCH   2
#define SEQ     2048
#define CDIM    1024
#define HEADS   16
#define HDIM    64
#define GAMMA_F 8.0f
#define SCALE_F 0.125f
#define MROWS   (BATCH*SEQ)          // 4096
#define KDIM    1024

// ---------------- scratch (device globals; no allocation allowed) ----------
// split-bf16 operands -- ALL stored in pre-swizzled tile-blocked layouts
__device__ __nv_bfloat16 g_xh [MROWS * CDIM];
__device__ __nv_bfloat16 g_xl [MROWS * CDIM];
__device__ __nv_bfloat16 g_ah [MROWS * CDIM];
__device__ __nv_bfloat16 g_al [MROWS * CDIM];
__device__ __nv_bfloat16 g_wqh[2 * CDIM * CDIM];
__device__ __nv_bfloat16 g_wql[2 * CDIM * CDIM];
__device__ __nv_bfloat16 g_wkh[2 * CDIM * CDIM];
__device__ __nv_bfloat16 g_wkl[2 * CDIM * CDIM];
__device__ __nv_bfloat16 g_wvh[CDIM * CDIM];
__device__ __nv_bfloat16 g_wvl[CDIM * CDIM];
__device__ __nv_bfloat16 g_woh[CDIM * CDIM];
__device__ __nv_bfloat16 g_wol[CDIM * CDIM];

// attention operands, split bf16, attention tile layout
__device__ __nv_bfloat16 g_qrh[MROWS * CDIM];
__device__ __nv_bfloat16 g_qrl[MROWS * CDIM];
__device__ __nv_bfloat16 g_qih[MROWS * CDIM];
__device__ __nv_bfloat16 g_qil[MROWS * CDIM];
__device__ __nv_bfloat16 g_krh[MROWS * CDIM];
__device__ __nv_bfloat16 g_krl[MROWS * CDIM];
__device__ __nv_bfloat16 g_kih[MROWS * CDIM];
__device__ __nv_bfloat16 g_kil[MROWS * CDIM];
__device__ __nv_bfloat16 g_vh [MROWS * CDIM];
__device__ __nv_bfloat16 g_vl [MROWS * CDIM];
__device__ float2 g_gate[HEADS * SEQ];

// ---------------- helpers ---------------------------------------------------
__device__ __forceinline__ uint32_t smem_u32(const void* p) {
    uint32_t a;
    asm("{ .reg .u64 t; cvta.to.shared.u64 t, %1; cvt.u32.u64 %0, t; }"
        : "=r"(a) : "l"(p));
    return a;
}
#define SWZ128(o) ((o) ^ (((o) >> 3) & 0x70))

// GEMM A-operand layout: [mb=row/128][kc=col/64][r=row%128][swizzled 128B row]
__device__ __forceinline__ size_t gemmA_off(int row, int col) {
    return ((size_t)((row >> 7) * 16 + (col >> 6)) << 14) +
           SWZ128((uint32_t)((row & 127) * 128 + (col & 63) * 2));
}
// Attention layout: [b][h][sb=t/64][r=t%64][swizzled 128B row]
__device__ __forceinline__ size_t att_off(int b, int h, int t, int d) {
    return ((size_t)((b * HEADS + h) * 32 + (t >> 6)) << 13) +
           SWZ128((uint32_t)((t & 63) * 128 + d * 2));
}

#define MBARRIER_INIT(mbar, count) \
    asm volatile("mbarrier.init.shared.b64 [%0], %1;" :: "r"((uint32_t)(mbar)), "r"((uint32_t)(count)) : "memory")
#define MBAR_EXPECT(mbar, bytes) \
    asm volatile("mbarrier.arrive.expect_tx.shared.b64 _, [%0], %1;" :: "r"((uint32_t)(mbar)), "r"((uint32_t)(bytes)) : "memory")

#define MBARRIER_WAIT_PARITY(mbar, parity) do { \
    uint32_t _m = (uint32_t)(mbar); uint32_t _p = (uint32_t)(parity); uint32_t _d; \
    asm volatile("{\n\t.reg .pred p;\n\t" \
        "mbarrier.try_wait.parity.acquire.cta.shared::cta.b64 p, [%1], %2;\n\t" \
        "selp.b32 %0, 1, 0, p;\n\t}" : "=r"(_d) : "r"(_m), "r"(_p) : "memory"); \
    if (!_d) { \
        asm volatile("{\n\t.reg .pred P1;\n\t" \
            "WL_%=:\n\t" \
            "mbarrier.try_wait.parity.acquire.cta.shared::cta.b64 P1, [%0], %1, 0x989680;\n\t" \
            "@P1 bra.uni WD_%=;\n\tbra.uni WL_%=;\n\tWD_%=:\n\t}" \
            :: "r"(_m), "r"(_p) : "memory"); \
    } } while (0)

__device__ __forceinline__ void bulk_g2s(uint32_t dst, const void* src,
                                         uint32_t bytes, uint32_t mbar) {
    asm volatile(
        "cp.async.bulk.shared::cluster.global.mbarrier::complete_tx::bytes [%0], [%1], %2, [%3];"
        :: "r"(dst), "l"(src), "r"(bytes), "r"(mbar) : "memory");
}

__device__ __forceinline__ void ldsm_x4(uint32_t& r0, uint32_t& r1,
                                        uint32_t& r2, uint32_t& r3, uint32_t addr) {
    asm volatile("ldmatrix.sync.aligned.m8n8.x4.shared.b16 {%0,%1,%2,%3}, [%4];"
                 : "=r"(r0), "=r"(r1), "=r"(r2), "=r"(r3) : "r"(addr));
}
__device__ __forceinline__ void ldsm_x4_t(uint32_t& r0, uint32_t& r1,
                                          uint32_t& r2, uint32_t& r3, uint32_t addr) {
    asm volatile("ldmatrix.sync.aligned.m8n8.x4.trans.shared.b16 {%0,%1,%2,%3}, [%4];"
                 : "=r"(r0), "=r"(r1), "=r"(r2), "=r"(r3) : "r"(addr));
}

__device__ __forceinline__ void mma_bf16(float* c, const uint32_t* a,
                                         uint32_t b0, uint32_t b1) {
    asm volatile(
        "mma.sync.aligned.m16n8k16.row.col.f32.bf16.bf16.f32 "
        "{%0,%1,%2,%3}, {%4,%5,%6,%7}, {%8,%9}, {%0,%1,%2,%3};"
        : "+f"(c[0]), "+f"(c[1]), "+f"(c[2]), "+f"(c[3])
        : "r"(a[0]), "r"(a[1]), "r"(a[2]), "r"(a[3]), "r"(b0), "r"(b1));
}

__device__ __forceinline__ uint32_t pack_bf16(float a, float b) {
    __nv_bfloat162 t = __float22bfloat162_rn(make_float2(a, b));
    return *reinterpret_cast<uint32_t*>(&t);
}

__device__ __forceinline__ float softplus_f(float a) {
    return (a > 20.f) ? a : log1pf(expf(a));
}

// ---------------- shared GEMM mainloop (block 128x256, 8 warps 64x64) -------
#define BK       64
#define NCH      (KDIM / BK)             // 16
#define A_TB     16384
#define B_TB     32768
#define STG_B    (2 * A_TB + 2 * B_TB)   // 98304
#define GEMM_SMEM (1024 + 2 * STG_B)     // 197632

__device__ __forceinline__ void gemm_mainloop(
    const char* cAh, const char* cAl, const char* cBh, const char* cBl,
    float acc[4][8][4]) {
    extern __shared__ char smem[];
    const uint32_t sb = smem_u32(smem);
    const int tid = threadIdx.x, wid = tid >> 5, lane = tid & 31;
    const int wm = (wid & 1) * 64;
    const int wn = (wid >> 1) * 64;

    const size_t mbB = ((size_t)blockIdx.y * 16) << 14;
    const size_t nbB0 = ((size_t)(blockIdx.x * 2) * 16) << 14;
    const size_t nbB1 = ((size_t)(blockIdx.x * 2 + 1) * 16) << 14;

    if (tid == 0) { MBARRIER_INIT(sb, 1); MBARRIER_INIT(sb + 8, 1); }
    __syncthreads();

    auto issue = [&](int chunk, int buf) {
        const uint32_t st = sb + 1024 + buf * STG_B;
        const uint32_t bar = sb + buf * 8;
        const size_t kB = ((size_t)chunk) << 14;
        MBAR_EXPECT(bar, STG_B);
        bulk_g2s(st,             cAh + mbB + kB,  A_TB, bar);
        bulk_g2s(st + A_TB,      cAl + mbB + kB,  A_TB, bar);
        bulk_g2s(st + 2 * A_TB,          cBh + nbB0 + kB, A_TB, bar);
        bulk_g2s(st + 2 * A_TB + A_TB,   cBh + nbB1 + kB, A_TB, bar);
        bulk_g2s(st + 2 * A_TB + B_TB,        cBl + nbB0 + kB, A_TB, bar);
        bulk_g2s(st + 2 * A_TB + B_TB + A_TB, cBl + nbB1 + kB, A_TB, bar);
    };

    if (tid == 0) { issue(0, 0); issue(1, 1); }

#pragma unroll
    for (int i = 0; i < 4; i++)
#pragma unroll
        for (int j = 0; j < 8; j++)
#pragma unroll
            for (int e = 0; e < 4; e++) acc[i][j][e] = 0.f;

    const int a_row = (lane & 15);
    const uint32_t a_cb = (uint32_t)((lane >> 4) * 16);
    const int b_row = ((lane >> 4) & 1) * 8 + (lane & 7);
    const uint32_t b_cb = (uint32_t)(((lane >> 3) & 1) * 16);

    for (int i = 0; i < NCH; i++) {
        MBARRIER_WAIT_PARITY(sb + (i & 1) * 8, (i >> 1) & 1);

        const uint32_t st = sb + 1024 + (i & 1) * STG_B;
        const uint32_t aH = st, aL = st + A_TB;
        const uint32_t bH = st + 2 * A_TB, bL = st + 2 * A_TB + B_TB;

#pragma unroll
        for (int ks = 0; ks < 4; ks++) {
            const uint32_t kb = (uint32_t)(ks * 32);
            uint32_t ah[4][4], al[4][4];
#pragma unroll
            for (int mi = 0; mi < 4; mi++) {
                uint32_t off = SWZ128((uint32_t)((wm + mi * 16 + a_row) * 128) + kb + a_cb);
                ldsm_x4(ah[mi][0], ah[mi][1], ah[mi][2], ah[mi][3], aH + off);
                ldsm_x4(al[mi][0], al[mi][1], al[mi][2], al[mi][3], aL + off);
            }
#pragma unroll
            for (int ng = 0; ng < 4; ng++) {
                uint32_t off = SWZ128((uint32_t)((wn + ng * 16 + b_row) * 128) + kb + b_cb);
                uint32_t bh[4], bl[4];
                ldsm_x4(bh[0], bh[1], bh[2], bh[3], bH + off);
                ldsm_x4(bl[0], bl[1], bl[2], bl[3], bL + off);
#pragma unroll
                for (int mi = 0; mi < 4; mi++) {
                    mma_bf16(acc[mi][2 * ng],     ah[mi], bh[0], bh[1]);
                    mma_bf16(acc[mi][2 * ng],     ah[mi], bl[0], bl[1]);
                    mma_bf16(acc[mi][2 * ng],     al[mi], bh[0], bh[1]);
                    mma_bf16(acc[mi][2 * ng + 1], ah[mi], bh[2], bh[3]);
                    mma_bf16(acc[mi][2 * ng + 1], ah[mi], bl[2], bl[3]);
                    mma_bf16(acc[mi][2 * ng + 1], al[mi], bh[2], bh[3]);
                }
            }
        }
        __syncthreads();
        if (i + 2 < NCH && tid == 0) issue(i + 2, i & 1);
    }
}

// ---------------- GEMM with fp32 epilogue (final output projection) ---------
__global__ __launch_bounds__(256, 1)
void gemm_bf16x3(const __nv_bfloat16* __restrict__ Ah, const __nv_bfloat16* __restrict__ Al,
                 const __nv_bfloat16* __restrict__ Bh, const __nv_bfloat16* __restrict__ Bl,
                 float* __restrict__ Cm, int N) {
    float acc[4][8][4];
    gemm_mainloop((const char*)Ah, (const char*)Al, (const char*)Bh, (const char*)Bl, acc);

    const int tid = threadIdx.x, wid = tid >> 5, lane = tid & 31;
    const int m0 = blockIdx.y * 128, n0 = blockIdx.x * 256;
    const int wm = (wid & 1) * 64, wn = (wid >> 1) * 64;
    const int cr = lane >> 2;
    const int cc = (lane & 3) * 2;
#pragma unroll
    for (int mi = 0; mi < 4; mi++) {
#pragma unroll
        for (int nj = 0; nj < 8; nj++) {
            const int r = m0 + wm + mi * 16 + cr;
            const int c = n0 + wn + nj * 8 + cc;
            *(float2*)&Cm[(size_t)r * N + c] = make_float2(acc[mi][nj][0], acc[mi][nj][1]);
            *(float2*)&Cm[(size_t)(r + 8) * N + c] = make_float2(acc[mi][nj][2], acc[mi][nj][3]);
        }
    }
}

// ---------------- Q/K GEMM with fused amp/phase epilogue --------------------
// Weights are column-permuted so col 2c = amp(c), col 2c+1 = phase(c).
__global__ __launch_bounds__(256, 1)
void gemm_qk_fused(const __nv_bfloat16* __restrict__ Ah, const __nv_bfloat16* __restrict__ Al,
                   const __nv_bfloat16* __restrict__ Bh, const __nv_bfloat16* __restrict__ Bl,
                   __nv_bfloat16* __restrict__ Rh, __nv_bfloat16* __restrict__ Rl,
                   __nv_bfloat16* __restrict__ Ih, __nv_bfloat16* __restrict__ Il) {
    float acc[4][8][4];
    gemm_mainloop((const char*)Ah, (const char*)Al, (const char*)Bh, (const char*)Bl, acc);

    const int tid = threadIdx.x, wid = tid >> 5, lane = tid & 31;
    const int m0 = blockIdx.y * 128, n0 = blockIdx.x * 256;
    const int wm = (wid & 1) * 64, wn = (wid >> 1) * 64;
    const int cr = lane >> 2;
    const int cc = (lane & 3) * 2;
#pragma unroll
    for (int mi = 0; mi < 4; mi++) {
#pragma unroll
        for (int nj = 0; nj < 8; nj++) {
            const int c = n0 + wn + nj * 8 + cc;   // even
            const int ch = c >> 1;
            const int h = ch >> 6, d = ch & 63;
#pragma unroll
            for (int rr = 0; rr < 2; rr++) {
                const int r = m0 + wm + mi * 16 + cr + rr * 8;
                const int b = r >> 11, t = r & (SEQ - 1);
                const float amp = acc[mi][nj][2 * rr];
                const float ph  = acc[mi][nj][2 * rr + 1];
                const float qs = softplus_f(amp);
                float sn, cs;
                sincosf(ph, &sn, &cs);
                const float re = qs * cs, im = qs * sn;
                const __nv_bfloat16 reh = __float2bfloat16(re);
                const __nv_bfloat16 imh = __float2bfloat16(im);
                const size_t off = att_off(b, h, t, d);
                *(__nv_bfloat16*)((char*)Rh + off) = reh;
                *(__nv_bfloat16*)((char*)Rl + off) =
                    __float2bfloat16(re - __bfloat162float(reh));
                *(__nv_bfloat16*)((char*)Ih + off) = imh;
                *(__nv_bfloat16*)((char*)Il + off) =
                    __float2bfloat16(im - __bfloat162float(imh));
            }
        }
    }
}

// ---------------- V GEMM with fused hi/lo split epilogue --------------------
__global__ __launch_bounds__(256, 1)
void gemm_v_fused(const __nv_bfloat16* __restrict__ Ah, const __nv_bfloat16* __restrict__ Al,
                  const __nv_bfloat16* __restrict__ Bh, const __nv_bfloat16* __restrict__ Bl,
                  __nv_bfloat16* __restrict__ Vh, __nv_bfloat16* __restrict__ Vl) {
    float acc[4][8][4];
    gemm_mainloop((const char*)Ah, (const char*)Al, (const char*)Bh, (const char*)Bl, acc);

    const int tid = threadIdx.x, wid = tid >> 5, lane = tid & 31;
    const int m0 = blockIdx.y * 128, n0 = blockIdx.x * 256;
    const int wm = (wid & 1) * 64, wn = (wid >> 1) * 64;
    const int cr = lane >> 2;
    const int cc = (lane & 3) * 2;
#pragma unroll
    for (int mi = 0; mi < 4; mi++) {
#pragma unroll
        for (int nj = 0; nj < 8; nj++) {
            const int c = n0 + wn + nj * 8 + cc;   // even; c,c+1 same head
            const int h = c >> 6, d = c & 63;
#pragma unroll
            for (int rr = 0; rr < 2; rr++) {
                const int r = m0 + wm + mi * 16 + cr + rr * 8;
                const int b = r >> 11, t = r & (SEQ - 1);
                const float v0 = acc[mi][nj][2 * rr];
                const float v1 = acc[mi][nj][2 * rr + 1];
                const float h0 = __bfloat162float(__float2bfloat16(v0));
                const float h1 = __bfloat162float(__float2bfloat16(v1));
                const size_t off = att_off(b, h, t, d);   // 4B-aligned (d even)
                *(uint32_t*)((char*)Vh + off) = pack_bf16(h0, h1);
                *(uint32_t*)((char*)Vl + off) = pack_bf16(v0 - h0, v1 - h1);
            }
        }
    }
}

// ---------------- fp32 -> (hi,lo) bf16 split, GEMM-A tiled layout ----------
__global__ __launch_bounds__(256)
void convert_split_gemm(const float* __restrict__ src, __nv_bfloat16* __restrict__ hi,
                        __nv_bfloat16* __restrict__ lo) {
    int i2 = blockIdx.x * 256 + threadIdx.x;
    int row = i2 >> 9, col = (i2 & 511) * 2;
    float2 v = *(const float2*)&src[(size_t)row * CDIM + col];
    __nv_bfloat16 h0 = __float2bfloat16(v.x), h1 = __float2bfloat16(v.y);
    size_t off = gemmA_off(row, col);
    *(uint32_t*)((char*)hi + off) = pack_bf16(__bfloat162float(h0), __bfloat162float(h1));
    *(uint32_t*)((char*)lo + off) = pack_bf16(v.x - __bfloat162float(h0),
                                              v.y - __bfloat162float(h1));
}

// ---------------- weight transpose + split -> GEMM-A tiled layout ----------
__global__ __launch_bounds__(256)
void transpose_split(const float* __restrict__ W, __nv_bfloat16* __restrict__ Hh,
                     __nv_bfloat16* __restrict__ Hl, int K, int N) {
    __shared__ float t[32][33];
    const int tx = threadIdx.x, ty = threadIdx.y;
    const int n0 = blockIdx.x * 32, k0 = blockIdx.y * 32;
#pragma unroll
    for (int i = 0; i < 32; i += 8)
        t[ty + i][tx] = W[(size_t)(k0 + ty + i) * N + n0 + tx];
    __syncthreads();
#pragma unroll
    for (int i = 0; i < 32; i += 8) {
        float v = t[tx][ty + i];
        __nv_bfloat16 h = __float2bfloat16(v);
        size_t off = gemmA_off(n0 + ty + i, k0 + tx);
        *(__nv_bfloat16*)((char*)Hh + off) = h;
        *(__nv_bfloat16*)((char*)Hl + off) = __float2bfloat16(v - __bfloat162float(h));
    }
}

// Q/K variant: permute output rows so amp ch c -> 2c, phase ch c -> 2c+1
__global__ __launch_bounds__(256)
void transpose_split_qk(const float* __restrict__ W, __nv_bfloat16* __restrict__ Hh,
                        __nv_bfloat16* __restrict__ Hl, int K, int N) {
    __shared__ float t[32][33];
    const int tx = threadIdx.x, ty = threadIdx.y;
    const int n0 = blockIdx.x * 32, k0 = blockIdx.y * 32;
#pragma unroll
    for (int i = 0; i < 32; i += 8)
        t[ty + i][tx] = W[(size_t)(k0 + ty + i) * N + n0 + tx];
    __syncthreads();
#pragma unroll
    for (int i = 0; i < 32; i += 8) {
        float v = t[tx][ty + i];
        __nv_bfloat16 h = __float2bfloat16(v);
        int n = n0 + ty + i;
        int pn = (n < CDIM) ? (2 * n) : (2 * (n - CDIM) + 1);
        size_t off = gemmA_off(pn, k0 + tx);
        *(__nv_bfloat16*)((char*)Hh + off) = h;
        *(__nv_bfloat16*)((char*)Hl + off) = __float2bfloat16(v - __bfloat162float(h));
    }
}

__global__ void gate_init(const float* __restrict__ theta) {
    int i = blockIdx.x * 256 + threadIdx.x;
    int h = i >> 11, s = i & (SEQ - 1);
    float th = theta[h] * (1.0f / GAMMA_F);
    float sn, cs;
    sincosf(th * (float)s, &sn, &cs);
    g_gate[i] = make_float2(cs, sn);
}

// ---------------- tensor-core flash attention with moiré gate ---------------
#define AQT 128
#define AST 64
#define AQ_TILE 16384
#define AKV_TILE 8192
#define AKV_BUF (6 * AKV_TILE)
#define ATT_SMEM (1024 + 4 * AQ_TILE + 2 * AKV_BUF)  // 164864

__global__ __launch_bounds__(256)
void attn_mma() {
    extern __shared__ char smem[];
    const uint32_t sb = smem_u32(smem);
    const uint32_t sQ  = sb + 1024;
    const uint32_t sKV = sQ + 4 * AQ_TILE;

    const int tid = threadIdx.x, w = tid >> 5, lane = tid & 31;
    const int q0 = (int)(gridDim.x - 1 - blockIdx.x) * AQT;
    const int h = blockIdx.y, b = blockIdx.z;
    const int nS = q0 / AST + 2;

    const size_t bhB = ((size_t)((b * HEADS + h) * 32)) << 13;

    if (tid == 0) {
        MBARRIER_INIT(sb, 1);
        MBARRIER_INIT(sb + 8, 1);
        MBARRIER_INIT(sb + 16, 1);
    }
    __syncthreads();

    auto issue_kv = [&](int chunk, int buf) {
        const uint32_t st = sKV + buf * AKV_BUF;
        const uint32_t bar = sb + 8 + buf * 8;
        const size_t src = bhB + (((size_t)chunk) << 13);
        MBAR_EXPECT(bar, AKV_BUF);
        bulk_g2s(st,                (const char*)g_krh + src, AKV_TILE, bar);
        bulk_g2s(st + AKV_TILE,     (const char*)g_krl + src, AKV_TILE, bar);
        bulk_g2s(st + 2 * AKV_TILE, (const char*)g_kih + src, AKV_TILE, bar);
        bulk_g2s(st + 3 * AKV_TILE, (const char*)g_kil + src, AKV_TILE, bar);
        bulk_g2s(st + 4 * AKV_TILE, (const char*)g_vh  + src, AKV_TILE, bar);
        bulk_g2s(st + 5 * AKV_TILE, (const char*)g_vl  + src, AKV_TILE, bar);
    };

    if (tid == 0) {
        const size_t qsrc = bhB + (((size_t)(q0 >> 6)) << 13);
        MBAR_EXPECT(sb, 4 * AQ_TILE);
        bulk_g2s(sQ,               (const char*)g_qrh + qsrc, AQ_TILE, sb);
        bulk_g2s(sQ + AQ_TILE,     (const char*)g_qrl + qsrc, AQ_TILE, sb);
        bulk_g2s(sQ + 2 * AQ_TILE, (const char*)g_qih + qsrc, AQ_TILE, sb);
        bulk_g2s(sQ + 3 * AQ_TILE, (const char*)g_qil + qsrc, AQ_TILE, sb);
        issue_kv(0, 0);
        issue_kv(1, 1);
    }

    const int a_row = lane & 15;
    const uint32_t a_cb = (uint32_t)((lane >> 4) * 16);
    const int b_row = ((lane >> 4) & 1) * 8 + (lane & 7);
    const uint32_t b_cb = (uint32_t)(((lane >> 3) & 1) * 16);

    const int t0g = q0 + w * 16 + (lane >> 2);
    const int t1g = t0g + 8;
    const float2 gt0 = g_gate[h * SEQ + t0g];
    const float2 gt1 = g_gate[h * SEQ + t1g];

    float m0 = -INFINITY, m1 = -INFINITY, l0 = 0.f, l1 = 0.f;
    float oacc[8][4];
#pragma unroll
    for (int f = 0; f < 8; f++)
#pragma unroll
        for (int e = 0; e < 4; e++) oacc[f][e] = 0.f;

    MBARRIER_WAIT_PARITY(sb, 0);

    for (int i = 0; i < nS; i++) {
        MBARRIER_WAIT_PARITY(sb + 8 + (i & 1) * 8, (i >> 1) & 1);

        const int s0 = i * AST;
        const uint32_t kb0 = sKV + (i & 1) * AKV_BUF;
        const uint32_t kRH = kb0, kRL = kb0 + AKV_TILE;
        const uint32_t kIH = kb0 + 2 * AKV_TILE, kIL = kb0 + 3 * AKV_TILE;
        const uint32_t vH = kb0 + 4 * AKV_TILE, vL = kb0 + 5 * AKV_TILE;

        float sacc[8][4];
#pragma unroll
        for (int f = 0; f < 8; f++)
#pragma unroll
            for (int e = 0; e < 4; e++) sacc[f][e] = 0.f;

#pragma unroll
        for (int jd = 0; jd < 4; jd++) {
            const uint32_t kb = (uint32_t)(jd * 32);
            const uint32_t offA = SWZ128((uint32_t)((w * 16 + a_row) * 128) + kb + a_cb);
            uint32_t arh[4], arl[4], aih[4], ail[4];
            ldsm_x4(arh[0], arh[1], arh[2], arh[3], sQ + offA);
            ldsm_x4(arl[0], arl[1], arl[2], arl[3], sQ + AQ_TILE + offA);
            ldsm_x4(aih[0], aih[1], aih[2], aih[3], sQ + 2 * AQ_TILE + offA);
            ldsm_x4(ail[0], ail[1], ail[2], ail[3], sQ + 3 * AQ_TILE + offA);
#pragma unroll
            for (int g = 0; g < 4; g++) {
                const uint32_t offB = SWZ128((uint32_t)((g * 16 + b_row) * 128) + kb + b_cb);
                uint32_t rh[4], rl[4], ih[4], il[4];
                ldsm_x4(rh[0], rh[1], rh[2], rh[3], kRH + offB);
                ldsm_x4(rl[0], rl[1], rl[2], rl[3], kRL + offB);
                ldsm_x4(ih[0], ih[1], ih[2], ih[3], kIH + offB);
                ldsm_x4(il[0], il[1], il[2], il[3], kIL + offB);
                mma_bf16(sacc[2 * g],     arh, rh[0], rh[1]);
                mma_bf16(sacc[2 * g],     arl, rh[0], rh[1]);
                mma_bf16(sacc[2 * g],     arh, rl[0], rl[1]);
                mma_bf16(sacc[2 * g],     aih, ih[0], ih[1]);
                mma_bf16(sacc[2 * g],     ail, ih[0], ih[1]);
                mma_bf16(sacc[2 * g],     aih, il[0], il[1]);
                mma_bf16(sacc[2 * g + 1], arh, rh[2], rh[3]);
                mma_bf16(sacc[2 * g + 1], arl, rh[2], rh[3]);
                mma_bf16(sacc[2 * g + 1], arh, rl[2], rl[3]);
                mma_bf16(sacc[2 * g + 1], aih, ih[2], ih[3]);
                mma_bf16(sacc[2 * g + 1], ail, ih[2], ih[3]);
                mma_bf16(sacc[2 * g + 1], aih, il[2], il[3]);
            }
        }

        float pm0 = -INFINITY, pm1 = -INFINITY;
#pragma unroll
        for (int f = 0; f < 8; f++) {
            const int sb2 = s0 + f * 8 + (lane & 3) * 2;
            const float2 gs0 = g_gate[h * SEQ + sb2];
            const float2 gs1 = g_gate[h * SEQ + sb2 + 1];
            float v00 = sacc[f][0] * SCALE_F * (gs0.x * gt0.x + gs0.y * gt0.y);
            float v01 = sacc[f][1] * SCALE_F * (gs1.x * gt0.x + gs1.y * gt0.y);
            float v10 = sacc[f][2] * SCALE_F * (gs0.x * gt1.x + gs0.y * gt1.y);
            float v11 = sacc[f][3] * SCALE_F * (gs1.x * gt1.x + gs1.y * gt1.y);
            if (sb2 > t0g)     v00 = -INFINITY;
            if (sb2 + 1 > t0g) v01 = -INFINITY;
            if (sb2 > t1g)     v10 = -INFINITY;
            if (sb2 + 1 > t1g) v11 = -INFINITY;
            sacc[f][0] = v00; sacc[f][1] = v01; sacc[f][2] = v10; sacc[f][3] = v11;
            pm0 = fmaxf(pm0, fmaxf(v00, v01));
            pm1 = fmaxf(pm1, fmaxf(v10, v11));
        }
        pm0 = fmaxf(pm0, __shfl_xor_sync(0xffffffffu, pm0, 1));
        pm0 = fmaxf(pm0, __shfl_xor_sync(0xffffffffu, pm0, 2));
        pm1 = fmaxf(pm1, __shfl_xor_sync(0xffffffffu, pm1, 1));
        pm1 = fmaxf(pm1, __shfl_xor_sync(0xffffffffu, pm1, 2));

        const float mn0 = fmaxf(m0, pm0), mn1 = fmaxf(m1, pm1);
        const float cr0 = __expf(m0 - mn0), cr1 = __expf(m1 - mn1);
        float rs0 = 0.f, rs1 = 0.f;
#pragma unroll
        for (int f = 0; f < 8; f++) {
            sacc[f][0] = __expf(sacc[f][0] - mn0);
            sacc[f][1] = __expf(sacc[f][1] - mn0);
            sacc[f][2] = __expf(sacc[f][2] - mn1);
            sacc[f][3] = __expf(sacc[f][3] - mn1);
            rs0 += sacc[f][0] + sacc[f][1];
            rs1 += sacc[f][2] + sacc[f][3];
        }
        rs0 += __shfl_xor_sync(0xffffffffu, rs0, 1);
        rs0 += __shfl_xor_sync(0xffffffffu, rs0, 2);
        rs1 += __shfl_xor_sync(0xffffffffu, rs1, 1);
        rs1 += __shfl_xor_sync(0xffffffffu, rs1, 2);
        l0 = l0 * cr0 + rs0; m0 = mn0;
        l1 = l1 * cr1 + rs1; m1 = mn1;
#pragma unroll
        for (int f = 0; f < 8; f++) {
            oacc[f][0] *= cr0; oacc[f][1] *= cr0;
            oacc[f][2] *= cr1; oacc[f][3] *= cr1;
        }

#pragma unroll
        for (int j = 0; j < 4; j++) {
            float p00 = sacc[2 * j][0],     p01 = sacc[2 * j][1];
            float p02 = sacc[2 * j][2],     p03 = sacc[2 * j][3];
            float p10 = sacc[2 * j + 1][0], p11 = sacc[2 * j + 1][1];
            float p12 = sacc[2 * j + 1][2], p13 = sacc[2 * j + 1][3];
            float h00 = __bfloat162float(__float2bfloat16(p00));
            float h01 = __bfloat162float(__float2bfloat16(p01));
            float h02 = __bfloat162float(__float2bfloat16(p02));
            float h03 = __bfloat162float(__float2bfloat16(p03));
            float h10 = __bfloat162float(__float2bfloat16(p10));
            float h11 = __bfloat162float(__float2bfloat16(p11));
            float h12 = __bfloat162float(__float2bfloat16(p12));
            float h13 = __bfloat162float(__float2bfloat16(p13));
            uint32_t ph[4] = {pack_bf16(h00, h01), pack_bf16(h02, h03),
                              pack_bf16(h10, h11), pack_bf16(h12, h13)};
            uint32_t pl[4] = {pack_bf16(p00 - h00, p01 - h01), pack_bf16(p02 - h02, p03 - h03),
                              pack_bf16(p10 - h10, p11 - h11), pack_bf16(p12 - h12, p13 - h13)};
#pragma unroll
            for (int dg = 0; dg < 4; dg++) {
                const uint32_t offV = SWZ128((uint32_t)((16 * j + a_row) * 128) +
                                             (uint32_t)(dg * 32) + a_cb);
                uint32_t vh[4], vl[4];
                ldsm_x4_t(vh[0], vh[1], vh[2], vh[3], vH + offV);
                ldsm_x4_t(vl[0], vl[1], vl[2], vl[3], vL + offV);
                mma_bf16(oacc[2 * dg],     ph, vh[0], vh[1]);
                mma_bf16(oacc[2 * dg],     pl, vh[0], vh[1]);
                mma_bf16(oacc[2 * dg],     ph, vl[0], vl[1]);
                mma_bf16(oacc[2 * dg + 1], ph, vh[2], vh[3]);
                mma_bf16(oacc[2 * dg + 1], pl, vh[2], vh[3]);
                mma_bf16(oacc[2 * dg + 1], ph, vl[2], vl[3]);
            }
        }
        __syncthreads();
        if (i + 2 < nS && tid == 0) issue_kv(i + 2, i & 1);
    }

    const float iv0 = 1.0f / l0, iv1 = 1.0f / l1;
#pragma unroll
    for (int f = 0; f < 8; f++) {
        const int d = f * 8 + (lane & 3) * 2;
        float o00 = oacc[f][0] * iv0, o01 = oacc[f][1] * iv0;
        float o10 = oacc[f][2] * iv1, o11 = oacc[f][3] * iv1;
        float h00 = __bfloat162float(__float2bfloat16(o00));
        float h01 = __bfloat162float(__float2bfloat16(o01));
        float h10 = __bfloat162float(__float2bfloat16(o10));
        float h11 = __bfloat162float(__float2bfloat16(o11));
        size_t off0 = gemmA_off(b * SEQ + t0g, h * 64 + d);
        size_t off1 = gemmA_off(b * SEQ + t1g, h * 64 + d);
        *(uint32_t*)((char*)g_ah + off0) = pack_bf16(h00, h01);
        *(uint32_t*)((char*)g_al + off0) = pack_bf16(o00 - h00, o01 - h01);
        *(uint32_t*)((char*)g_ah + off1) = pack_bf16(h10, h11);
        *(uint32_t*)((char*)g_al + off1) = pack_bf16(o10 - h10, o11 - h11);
    }
}

// ---------------- launch ---------------------------------------------------
extern "C" void kernel_launch(void* const* d_in, const int* in_sizes, int n_in,
                              void* d_out, int out_size) {
    const float* x     = (const float*)d_in[0];
    const float* Wq    = (const float*)d_in[1];
    const float* Wk    = (const float*)d_in[2];
    const float* Wv    = (const float*)d_in[3];
    const float* Wo    = (const float*)d_in[4];
    const float* theta = (const float*)d_in[5];
    float* out = (float*)d_out;

    __nv_bfloat16 *xh, *xl, *ah, *al, *vh, *vl;
    __nv_bfloat16 *wqh, *wql, *wkh, *wkl, *wvh, *wvl, *woh, *wol;
    __nv_bfloat16 *qrh, *qrl, *qih, *qil, *krh, *krl, *kih, *kil;
    cudaGetSymbolAddress((void**)&xh,  g_xh);
    cudaGetSymbolAddress((void**)&xl,  g_xl);
    cudaGetSymbolAddress((void**)&ah,  g_ah);
    cudaGetSymbolAddress((void**)&al,  g_al);
    cudaGetSymbolAddress((void**)&vh,  g_vh);
    cudaGetSymbolAddress((void**)&vl,  g_vl);
    cudaGetSymbolAddress((void**)&wqh, g_wqh);
    cudaGetSymbolAddress((void**)&wql, g_wql);
    cudaGetSymbolAddress((void**)&wkh, g_wkh);
    cudaGetSymbolAddress((void**)&wkl, g_wkl);
    cudaGetSymbolAddress((void**)&wvh, g_wvh);
    cudaGetSymbolAddress((void**)&wvl, g_wvl);
    cudaGetSymbolAddress((void**)&woh, g_woh);
    cudaGetSymbolAddress((void**)&wol, g_wol);
    cudaGetSymbolAddress((void**)&qrh, g_qrh);
    cudaGetSymbolAddress((void**)&qrl, g_qrl);
    cudaGetSymbolAddress((void**)&qih, g_qih);
    cudaGetSymbolAddress((void**)&qil, g_qil);
    cudaGetSymbolAddress((void**)&krh, g_krh);
    cudaGetSymbolAddress((void**)&krl, g_krl);
    cudaGetSymbolAddress((void**)&kih, g_kih);
    cudaGetSymbolAddress((void**)&kil, g_kil);

    cudaFuncSetAttribute(gemm_bf16x3,
                         cudaFuncAttributeMaxDynamicSharedMemorySize, GEMM_SMEM);
    cudaFuncSetAttribute(gemm_qk_fused,
                         cudaFuncAttributeMaxDynamicSharedMemorySize, GEMM_SMEM);
    cudaFuncSetAttribute(gemm_v_fused,
                         cudaFuncAttributeMaxDynamicSharedMemorySize, GEMM_SMEM);
    cudaFuncSetAttribute(attn_mma,
                         cudaFuncAttributeMaxDynamicSharedMemorySize, ATT_SMEM);

    dim3 tblk(32, 8);

    convert_split_gemm<<<MROWS * CDIM / 2 / 256, 256>>>(x, xh, xl);
    gate_init<<<HEADS * SEQ / 256, 256>>>(theta);

    transpose_split_qk<<<dim3(2 * CDIM / 32, CDIM / 32), tblk>>>(Wq, wqh, wql, CDIM, 2 * CDIM);
    gemm_qk_fused<<<dim3(2 * CDIM / 256, MROWS / 128), 256, GEMM_SMEM>>>(
        xh, xl, wqh, wql, qrh, qrl, qih, qil);

    transpose_split_qk<<<dim3(2 * CDIM / 32, CDIM / 32), tblk>>>(Wk, wkh, wkl, CDIM, 2 * CDIM);
    gemm_qk_fused<<<dim3(2 * CDIM / 256, MROWS / 128), 256, GEMM_SMEM>>>(
        xh, xl, wkh, wkl, krh, krl, kih, kil);

    transpose_split<<<dim3(CDIM / 32, CDIM / 32), tblk>>>(Wv, wvh, wvl, CDIM, CDIM);
    gemm_v_fused<<<dim3(CDIM / 256, MROWS / 128), 256, GEMM_SMEM>>>(
        xh, xl, wvh, wvl, vh, vl);

    attn_mma<<<dim3(SEQ / AQT, HEADS, BATCH), 256, ATT_SMEM>>>();

    transpose_split<<<dim3(CDIM / 32, CDIM / 32), tblk>>>(Wo, woh, wol, CDIM, CDIM);
    gemm_bf16x3<<<dim3(CDIM / 256, MROWS / 128), 256, GEMM_SMEM>>>(ah, al, woh, wol, out, CDIM);
}

// round 8
// speedup vs baseline: 1.1379x; 1.1379x over previous
#include <cuda_runtime.h>
#include <cuda_bf16.h>
#include <cstdint>
#include <math.h>

// Problem constants
#define BATCH   2
#define SEQ     2048
#define CDIM    1024
#define HEADS   16
#define HDIM    64
#define GAMMA_F 8.0f
#define SCALE_F 0.125f
#define MROWS   (BATCH*SEQ)          // 4096
#define KDIM    1024

// ---------------- scratch (device globals; no allocation allowed) ----------
__device__ float g_qraw[MROWS * 2 * CDIM];
__device__ float g_kraw[MROWS * 2 * CDIM];
__device__ float g_v   [MROWS * CDIM];

// split-bf16 operands -- ALL stored in pre-swizzled tile-blocked layouts
__device__ __nv_bfloat16 g_xh [MROWS * CDIM];
__device__ __nv_bfloat16 g_xl [MROWS * CDIM];
__device__ __nv_bfloat16 g_ah [MROWS * CDIM];
__device__ __nv_bfloat16 g_al [MROWS * CDIM];
__device__ __nv_bfloat16 g_wqh[2 * CDIM * CDIM];
__device__ __nv_bfloat16 g_wql[2 * CDIM * CDIM];
__device__ __nv_bfloat16 g_wkh[2 * CDIM * CDIM];
__device__ __nv_bfloat16 g_wkl[2 * CDIM * CDIM];
__device__ __nv_bfloat16 g_wvh[CDIM * CDIM];
__device__ __nv_bfloat16 g_wvl[CDIM * CDIM];
__device__ __nv_bfloat16 g_woh[CDIM * CDIM];
__device__ __nv_bfloat16 g_wol[CDIM * CDIM];

// attention operands, split bf16, attention tile layout
__device__ __nv_bfloat16 g_qrh[MROWS * CDIM];
__device__ __nv_bfloat16 g_qrl[MROWS * CDIM];
__device__ __nv_bfloat16 g_qih[MROWS * CDIM];
__device__ __nv_bfloat16 g_qil[MROWS * CDIM];
__device__ __nv_bfloat16 g_krh[MROWS * CDIM];
__device__ __nv_bfloat16 g_krl[MROWS * CDIM];
__device__ __nv_bfloat16 g_kih[MROWS * CDIM];
__device__ __nv_bfloat16 g_kil[MROWS * CDIM];
__device__ __nv_bfloat16 g_vh [MROWS * CDIM];
__device__ __nv_bfloat16 g_vl [MROWS * CDIM];
__device__ float2 g_gate[HEADS * SEQ];

// ---------------- helpers ---------------------------------------------------
__device__ __forceinline__ uint32_t smem_u32(const void* p) {
    uint32_t a;
    asm("{ .reg .u64 t; cvta.to.shared.u64 t, %1; cvt.u32.u64 %0, t; }"
        : "=r"(a) : "l"(p));
    return a;
}
#define SWZ128(o) ((o) ^ (((o) >> 3) & 0x70))

__device__ __forceinline__ size_t gemmA_off(int row, int col) {
    return ((size_t)((row >> 7) * 16 + (col >> 6)) << 14) +
           SWZ128((uint32_t)((row & 127) * 128 + (col & 63) * 2));
}
__device__ __forceinline__ size_t att_off(int b, int h, int t, int d) {
    return ((size_t)((b * HEADS + h) * 32 + (t >> 6)) << 13) +
           SWZ128((uint32_t)((t & 63) * 128 + d * 2));
}

#define MBARRIER_INIT(mbar, count) \
    asm volatile("mbarrier.init.shared.b64 [%0], %1;" :: "r"((uint32_t)(mbar)), "r"((uint32_t)(count)) : "memory")
#define MBAR_EXPECT(mbar, bytes) \
    asm volatile("mbarrier.arrive.expect_tx.shared.b64 _, [%0], %1;" :: "r"((uint32_t)(mbar)), "r"((uint32_t)(bytes)) : "memory")

#define MBARRIER_WAIT_PARITY(mbar, parity) do { \
    uint32_t _m = (uint32_t)(mbar); uint32_t _p = (uint32_t)(parity); uint32_t _d; \
    asm volatile("{\n\t.reg .pred p;\n\t" \
        "mbarrier.try_wait.parity.acquire.cta.shared::cta.b64 p, [%1], %2;\n\t" \
        "selp.b32 %0, 1, 0, p;\n\t}" : "=r"(_d) : "r"(_m), "r"(_p) : "memory"); \
    if (!_d) { \
        asm volatile("{\n\t.reg .pred P1;\n\t" \
            "WL_%=:\n\t" \
            "mbarrier.try_wait.parity.acquire.cta.shared::cta.b64 P1, [%0], %1, 0x989680;\n\t" \
            "@P1 bra.uni WD_%=;\n\tbra.uni WL_%=;\n\tWD_%=:\n\t}" \
            :: "r"(_m), "r"(_p) : "memory"); \
    } } while (0)

__device__ __forceinline__ void bulk_g2s(uint32_t dst, const void* src,
                                         uint32_t bytes, uint32_t mbar) {
    asm volatile(
        "cp.async.bulk.shared::cluster.global.mbarrier::complete_tx::bytes [%0], [%1], %2, [%3];"
        :: "r"(dst), "l"(src), "r"(bytes), "r"(mbar) : "memory");
}

__device__ __forceinline__ void ldsm_x4(uint32_t& r0, uint32_t& r1,
                                        uint32_t& r2, uint32_t& r3, uint32_t addr) {
    asm volatile("ldmatrix.sync.aligned.m8n8.x4.shared.b16 {%0,%1,%2,%3}, [%4];"
                 : "=r"(r0), "=r"(r1), "=r"(r2), "=r"(r3) : "r"(addr));
}
__device__ __forceinline__ void ldsm_x4_t(uint32_t& r0, uint32_t& r1,
                                          uint32_t& r2, uint32_t& r3, uint32_t addr) {
    asm volatile("ldmatrix.sync.aligned.m8n8.x4.trans.shared.b16 {%0,%1,%2,%3}, [%4];"
                 : "=r"(r0), "=r"(r1), "=r"(r2), "=r"(r3) : "r"(addr));
}

__device__ __forceinline__ void mma_bf16(float* c, const uint32_t* a,
                                         uint32_t b0, uint32_t b1) {
    asm volatile(
        "mma.sync.aligned.m16n8k16.row.col.f32.bf16.bf16.f32 "
        "{%0,%1,%2,%3}, {%4,%5,%6,%7}, {%8,%9}, {%0,%1,%2,%3};"
        : "+f"(c[0]), "+f"(c[1]), "+f"(c[2]), "+f"(c[3])
        : "r"(a[0]), "r"(a[1]), "r"(a[2]), "r"(a[3]), "r"(b0), "r"(b1));
}

__device__ __forceinline__ uint32_t pack_bf16(float a, float b) {
    __nv_bfloat162 t = __float22bfloat162_rn(make_float2(a, b));
    return *reinterpret_cast<uint32_t*>(&t);
}

// ---------------- split-bf16 GEMM: C[M,N] = A[M,K] * B[N,K]^T ---------------
// Block 128x256, 8 warps 64x64, K-chunk 64, cp.async.bulk, PASS-MAJOR MMAs.
#define BK       64
#define NCH      (KDIM / BK)
#define A_TB     16384
#define B_TB     32768
#define STG_B    (2 * A_TB + 2 * B_TB)   // 98304
#define GEMM_SMEM (1024 + 2 * STG_B)     // 197632

__global__ __launch_bounds__(256, 1)
void gemm_bf16x3(const __nv_bfloat16* __restrict__ Ah, const __nv_bfloat16* __restrict__ Al,
                 const __nv_bfloat16* __restrict__ Bh, const __nv_bfloat16* __restrict__ Bl,
                 float* __restrict__ Cm, int N) {
    extern __shared__ char smem[];
    const uint32_t sb = smem_u32(smem);
    const int tid = threadIdx.x, wid = tid >> 5, lane = tid & 31;
    const int m0 = blockIdx.y * 128, n0 = blockIdx.x * 256;
    const int wm = (wid & 1) * 64;
    const int wn = (wid >> 1) * 64;

    const char* cAh = (const char*)Ah;
    const char* cAl = (const char*)Al;
    const char* cBh = (const char*)Bh;
    const char* cBl = (const char*)Bl;
    const size_t mbB = ((size_t)blockIdx.y * 16) << 14;
    const size_t nbB0 = ((size_t)(blockIdx.x * 2) * 16) << 14;
    const size_t nbB1 = ((size_t)(blockIdx.x * 2 + 1) * 16) << 14;

    if (tid == 0) { MBARRIER_INIT(sb, 1); MBARRIER_INIT(sb + 8, 1); }
    __syncthreads();

    auto issue = [&](int chunk, int buf) {
        const uint32_t st = sb + 1024 + buf * STG_B;
        const uint32_t bar = sb + buf * 8;
        const size_t kB = ((size_t)chunk) << 14;
        MBAR_EXPECT(bar, STG_B);
        bulk_g2s(st,             cAh + mbB + kB,  A_TB, bar);
        bulk_g2s(st + A_TB,      cAl + mbB + kB,  A_TB, bar);
        bulk_g2s(st + 2 * A_TB,          cBh + nbB0 + kB, A_TB, bar);
        bulk_g2s(st + 2 * A_TB + A_TB,   cBh + nbB1 + kB, A_TB, bar);
        bulk_g2s(st + 2 * A_TB + B_TB,        cBl + nbB0 + kB, A_TB, bar);
        bulk_g2s(st + 2 * A_TB + B_TB + A_TB, cBl + nbB1 + kB, A_TB, bar);
    };

    if (tid == 0) { issue(0, 0); issue(1, 1); }

    float acc[4][8][4];
#pragma unroll
    for (int i = 0; i < 4; i++)
#pragma unroll
        for (int j = 0; j < 8; j++)
#pragma unroll
            for (int e = 0; e < 4; e++) acc[i][j][e] = 0.f;

    const int a_row = (lane & 15);
    const uint32_t a_cb = (uint32_t)((lane >> 4) * 16);
    const int b_row = ((lane >> 4) & 1) * 8 + (lane & 7);
    const uint32_t b_cb = (uint32_t)(((lane >> 3) & 1) * 16);

    for (int i = 0; i < NCH; i++) {
        MBARRIER_WAIT_PARITY(sb + (i & 1) * 8, (i >> 1) & 1);

        const uint32_t st = sb + 1024 + (i & 1) * STG_B;
        const uint32_t aH = st, aL = st + A_TB;
        const uint32_t bH = st + 2 * A_TB, bL = st + 2 * A_TB + B_TB;

#pragma unroll
        for (int ks = 0; ks < 4; ks++) {
            const uint32_t kb = (uint32_t)(ks * 32);
            uint32_t ah[4][4], al[4][4];
#pragma unroll
            for (int mi = 0; mi < 4; mi++) {
                uint32_t off = SWZ128((uint32_t)((wm + mi * 16 + a_row) * 128) + kb + a_cb);
                ldsm_x4(ah[mi][0], ah[mi][1], ah[mi][2], ah[mi][3], aH + off);
                ldsm_x4(al[mi][0], al[mi][1], al[mi][2], al[mi][3], aL + off);
            }
#pragma unroll
            for (int hb = 0; hb < 2; hb++) {
                uint32_t bh[2][4], bl[2][4];
#pragma unroll
                for (int g2 = 0; g2 < 2; g2++) {
                    const int ng = hb * 2 + g2;
                    uint32_t off = SWZ128((uint32_t)((wn + ng * 16 + b_row) * 128) + kb + b_cb);
                    ldsm_x4(bh[g2][0], bh[g2][1], bh[g2][2], bh[g2][3], bH + off);
                    ldsm_x4(bl[g2][0], bl[g2][1], bl[g2][2], bl[g2][3], bL + off);
                }
                // pass 1: Ah x Bh  (16 independent MMAs)
#pragma unroll
                for (int g2 = 0; g2 < 2; g2++)
#pragma unroll
                    for (int mi = 0; mi < 4; mi++) {
                        const int nj = 2 * (hb * 2 + g2);
                        mma_bf16(acc[mi][nj],     ah[mi], bh[g2][0], bh[g2][1]);
                        mma_bf16(acc[mi][nj + 1], ah[mi], bh[g2][2], bh[g2][3]);
                    }
                // pass 2: Ah x Bl
#pragma unroll
                for (int g2 = 0; g2 < 2; g2++)
#pragma unroll
                    for (int mi = 0; mi < 4; mi++) {
                        const int nj = 2 * (hb * 2 + g2);
                        mma_bf16(acc[mi][nj],     ah[mi], bl[g2][0], bl[g2][1]);
                        mma_bf16(acc[mi][nj + 1], ah[mi], bl[g2][2], bl[g2][3]);
                    }
                // pass 3: Al x Bh
#pragma unroll
                for (int g2 = 0; g2 < 2; g2++)
#pragma unroll
                    for (int mi = 0; mi < 4; mi++) {
                        const int nj = 2 * (hb * 2 + g2);
                        mma_bf16(acc[mi][nj],     al[mi], bh[g2][0], bh[g2][1]);
                        mma_bf16(acc[mi][nj + 1], al[mi], bh[g2][2], bh[g2][3]);
                    }
            }
        }
        __syncthreads();
        if (i + 2 < NCH && tid == 0) issue(i + 2, i & 1);
    }

    const int cr = lane >> 2;
    const int cc = (lane & 3) * 2;
#pragma unroll
    for (int mi = 0; mi < 4; mi++) {
#pragma unroll
        for (int nj = 0; nj < 8; nj++) {
            const int r = m0 + wm + mi * 16 + cr;
            const int c = n0 + wn + nj * 8 + cc;
            *(float2*)&Cm[(size_t)r * N + c] = make_float2(acc[mi][nj][0], acc[mi][nj][1]);
            *(float2*)&Cm[(size_t)(r + 8) * N + c] = make_float2(acc[mi][nj][2], acc[mi][nj][3]);
        }
    }
}

// ---------------- fp32 -> (hi,lo) bf16 split, GEMM-A tiled layout ----------
__global__ __launch_bounds__(256)
void convert_split_gemm(const float* __restrict__ src, __nv_bfloat16* __restrict__ hi,
                        __nv_bfloat16* __restrict__ lo) {
    int i2 = blockIdx.x * 256 + threadIdx.x;
    int row = i2 >> 9, col = (i2 & 511) * 2;
    float2 v = *(const float2*)&src[(size_t)row * CDIM + col];
    __nv_bfloat16 h0 = __float2bfloat16(v.x), h1 = __float2bfloat16(v.y);
    size_t off = gemmA_off(row, col);
    *(uint32_t*)((char*)hi + off) = pack_bf16(__bfloat162float(h0), __bfloat162float(h1));
    *(uint32_t*)((char*)lo + off) = pack_bf16(v.x - __bfloat162float(h0),
                                              v.y - __bfloat162float(h1));
}

// fp32 -> hi/lo in ATTENTION tiled layout (for V)
__global__ __launch_bounds__(256)
void convert_split_att(const float* __restrict__ src, __nv_bfloat16* __restrict__ hi,
                       __nv_bfloat16* __restrict__ lo) {
    int i2 = blockIdx.x * 256 + threadIdx.x;
    int bt = i2 >> 9, col = (i2 & 511) * 2;
    int b = bt >> 11, t = bt & (SEQ - 1);
    int h = col >> 6, d = col & 63;
    float2 v = *(const float2*)&src[(size_t)bt * CDIM + col];
    __nv_bfloat16 h0 = __float2bfloat16(v.x), h1 = __float2bfloat16(v.y);
    size_t off = att_off(b, h, t, d);
    *(uint32_t*)((char*)hi + off) = pack_bf16(__bfloat162float(h0), __bfloat162float(h1));
    *(uint32_t*)((char*)lo + off) = pack_bf16(v.x - __bfloat162float(h0),
                                              v.y - __bfloat162float(h1));
}

// ---------------- weight transpose + split -> GEMM-A tiled layout ----------
__global__ __launch_bounds__(256)
void transpose_split(const float* __restrict__ W, __nv_bfloat16* __restrict__ Hh,
                     __nv_bfloat16* __restrict__ Hl, int K, int N) {
    __shared__ float t[32][33];
    const int tx = threadIdx.x, ty = threadIdx.y;
    const int n0 = blockIdx.x * 32, k0 = blockIdx.y * 32;
#pragma unroll
    for (int i = 0; i < 32; i += 8)
        t[ty + i][tx] = W[(size_t)(k0 + ty + i) * N + n0 + tx];
    __syncthreads();
#pragma unroll
    for (int i = 0; i < 32; i += 8) {
        float v = t[tx][ty + i];
        __nv_bfloat16 h = __float2bfloat16(v);
        size_t off = gemmA_off(n0 + ty + i, k0 + tx);
        *(__nv_bfloat16*)((char*)Hh + off) = h;
        *(__nv_bfloat16*)((char*)Hl + off) = __float2bfloat16(v - __bfloat162float(h));
    }
}

// ---------------- amp/phase transform -> split bf16, attention layout -------
__device__ __forceinline__ float softplus_f(float a) {
    return (a > 20.f) ? a : log1pf(expf(a));
}
__device__ __forceinline__ void split_store(float a, float b, __nv_bfloat16* H,
                                            __nv_bfloat16* L, size_t off) {
    __nv_bfloat16 ha = __float2bfloat16(a), hb = __float2bfloat16(b);
    *(uint32_t*)((char*)H + off) = pack_bf16(__bfloat162float(ha), __bfloat162float(hb));
    *(uint32_t*)((char*)L + off) = pack_bf16(a - __bfloat162float(ha),
                                             b - __bfloat162float(hb));
}

__global__ __launch_bounds__(256)
void transform_qk_bf16() {
    int i2 = blockIdx.x * 256 + threadIdx.x;
    int c2 = i2 * 2;
    int bt = c2 >> 10;
    int c  = c2 & 1023;
    int b = bt >> 11, t = bt & (SEQ - 1);
    int h = c >> 6, d = c & 63;
    size_t rbase = (size_t)bt * (2 * CDIM);
    size_t off = att_off(b, h, t, d);

    float qa0 = g_qraw[rbase + c],        qa1 = g_qraw[rbase + c + 1];
    float qp0 = g_qraw[rbase + CDIM + c], qp1 = g_qraw[rbase + CDIM + c + 1];
    float ka0 = g_kraw[rbase + c],        ka1 = g_kraw[rbase + c + 1];
    float kp0 = g_kraw[rbase + CDIM + c], kp1 = g_kraw[rbase + CDIM + c + 1];

    float qs0 = softplus_f(qa0), qs1 = softplus_f(qa1);
    float ks0 = softplus_f(ka0), ks1 = softplus_f(ka1);
    float s0, c0, s1, c1, s2, c2f, s3, c3;
    sincosf(qp0, &s0, &c0); sincosf(qp1, &s1, &c1);
    sincosf(kp0, &s2, &c2f); sincosf(kp1, &s3, &c3);

    split_store(qs0 * c0, qs1 * c1, g_qrh, g_qrl, off);
    split_store(qs0 * s0, qs1 * s1, g_qih, g_qil, off);
    split_store(ks0 * c2f, ks1 * c3, g_krh, g_krl, off);
    split_store(ks0 * s2, ks1 * s3, g_kih, g_kil, off);
}

__global__ void gate_init(const float* __restrict__ theta) {
    int i = blockIdx.x * 256 + threadIdx.x;
    int h = i >> 11, s = i & (SEQ - 1);
    float th = theta[h] * (1.0f / GAMMA_F);
    float sn, cs;
    sincosf(th * (float)s, &sn, &cs);
    g_gate[i] = make_float2(cs, sn);
}

// ---------------- tensor-core flash attention with moiré gate ---------------
#define AQT 128
#define AST 64
#define AQ_TILE 16384
#define AKV_TILE 8192
#define AKV_BUF (6 * AKV_TILE)
#define ATT_SMEM (1024 + 4 * AQ_TILE + 2 * AKV_BUF)  // 164864

__global__ __launch_bounds__(256)
void attn_mma() {
    extern __shared__ char smem[];
    const uint32_t sb = smem_u32(smem);
    const uint32_t sQ  = sb + 1024;
    const uint32_t sKV = sQ + 4 * AQ_TILE;

    const int tid = threadIdx.x, w = tid >> 5, lane = tid & 31;
    const int q0 = (int)(gridDim.x - 1 - blockIdx.x) * AQT;
    const int h = blockIdx.y, b = blockIdx.z;
    const int nS = q0 / AST + 2;

    const size_t bhB = ((size_t)((b * HEADS + h) * 32)) << 13;

    if (tid == 0) {
        MBARRIER_INIT(sb, 1);
        MBARRIER_INIT(sb + 8, 1);
        MBARRIER_INIT(sb + 16, 1);
    }
    __syncthreads();

    auto issue_kv = [&](int chunk, int buf) {
        const uint32_t st = sKV + buf * AKV_BUF;
        const uint32_t bar = sb + 8 + buf * 8;
        const size_t src = bhB + (((size_t)chunk) << 13);
        MBAR_EXPECT(bar, AKV_BUF);
        bulk_g2s(st,                (const char*)g_krh + src, AKV_TILE, bar);
        bulk_g2s(st + AKV_TILE,     (const char*)g_krl + src, AKV_TILE, bar);
        bulk_g2s(st + 2 * AKV_TILE, (const char*)g_kih + src, AKV_TILE, bar);
        bulk_g2s(st + 3 * AKV_TILE, (const char*)g_kil + src, AKV_TILE, bar);
        bulk_g2s(st + 4 * AKV_TILE, (const char*)g_vh  + src, AKV_TILE, bar);
        bulk_g2s(st + 5 * AKV_TILE, (const char*)g_vl  + src, AKV_TILE, bar);
    };

    if (tid == 0) {
        const size_t qsrc = bhB + (((size_t)(q0 >> 6)) << 13);
        MBAR_EXPECT(sb, 4 * AQ_TILE);
        bulk_g2s(sQ,               (const char*)g_qrh + qsrc, AQ_TILE, sb);
        bulk_g2s(sQ + AQ_TILE,     (const char*)g_qrl + qsrc, AQ_TILE, sb);
        bulk_g2s(sQ + 2 * AQ_TILE, (const char*)g_qih + qsrc, AQ_TILE, sb);
        bulk_g2s(sQ + 3 * AQ_TILE, (const char*)g_qil + qsrc, AQ_TILE, sb);
        issue_kv(0, 0);
        issue_kv(1, 1);
    }

    const int a_row = lane & 15;
    const uint32_t a_cb = (uint32_t)((lane >> 4) * 16);
    const int b_row = ((lane >> 4) & 1) * 8 + (lane & 7);
    const uint32_t b_cb = (uint32_t)(((lane >> 3) & 1) * 16);

    const int t0g = q0 + w * 16 + (lane >> 2);
    const int t1g = t0g + 8;
    const float2 gt0 = g_gate[h * SEQ + t0g];
    const float2 gt1 = g_gate[h * SEQ + t1g];

    float m0 = -INFINITY, m1 = -INFINITY, l0 = 0.f, l1 = 0.f;
    float oacc[8][4];
#pragma unroll
    for (int f = 0; f < 8; f++)
#pragma unroll
        for (int e = 0; e < 4; e++) oacc[f][e] = 0.f;

    MBARRIER_WAIT_PARITY(sb, 0);

    for (int i = 0; i < nS; i++) {
        MBARRIER_WAIT_PARITY(sb + 8 + (i & 1) * 8, (i >> 1) & 1);

        const int s0 = i * AST;
        const uint32_t kb0 = sKV + (i & 1) * AKV_BUF;
        const uint32_t kRH = kb0, kRL = kb0 + AKV_TILE;
        const uint32_t kIH = kb0 + 2 * AKV_TILE, kIL = kb0 + 3 * AKV_TILE;
        const uint32_t vH = kb0 + 4 * AKV_TILE, vL = kb0 + 5 * AKV_TILE;

        float sacc[8][4];
#pragma unroll
        for (int f = 0; f < 8; f++)
#pragma unroll
            for (int e = 0; e < 4; e++) sacc[f][e] = 0.f;

#pragma unroll
        for (int jd = 0; jd < 4; jd++) {
            const uint32_t kb = (uint32_t)(jd * 32);
            const uint32_t offA = SWZ128((uint32_t)((w * 16 + a_row) * 128) + kb + a_cb);
            uint32_t arh[4], arl[4], aih[4], ail[4];
            ldsm_x4(arh[0], arh[1], arh[2], arh[3], sQ + offA);
            ldsm_x4(arl[0], arl[1], arl[2], arl[3], sQ + AQ_TILE + offA);
            ldsm_x4(aih[0], aih[1], aih[2], aih[3], sQ + 2 * AQ_TILE + offA);
            ldsm_x4(ail[0], ail[1], ail[2], ail[3], sQ + 3 * AQ_TILE + offA);
#pragma unroll
            for (int gp = 0; gp < 2; gp++) {
                uint32_t rh[2][4], rl[2][4], ih[2][4], il[2][4];
#pragma unroll
                for (int g2 = 0; g2 < 2; g2++) {
                    const int g = gp * 2 + g2;
                    const uint32_t offB = SWZ128((uint32_t)((g * 16 + b_row) * 128) + kb + b_cb);
                    ldsm_x4(rh[g2][0], rh[g2][1], rh[g2][2], rh[g2][3], kRH + offB);
                    ldsm_x4(rl[g2][0], rl[g2][1], rl[g2][2], rl[g2][3], kRL + offB);
                    ldsm_x4(ih[g2][0], ih[g2][1], ih[g2][2], ih[g2][3], kIH + offB);
                    ldsm_x4(il[g2][0], il[g2][1], il[g2][2], il[g2][3], kIL + offB);
                }
                // 6 passes x 4 independent MMAs
#pragma unroll
                for (int g2 = 0; g2 < 2; g2++) {
                    const int s2 = 2 * (gp * 2 + g2);
                    mma_bf16(sacc[s2],     arh, rh[g2][0], rh[g2][1]);
                    mma_bf16(sacc[s2 + 1], arh, rh[g2][2], rh[g2][3]);
                }
#pragma unroll
                for (int g2 = 0; g2 < 2; g2++) {
                    const int s2 = 2 * (gp * 2 + g2);
                    mma_bf16(sacc[s2],     aih, ih[g2][0], ih[g2][1]);
                    mma_bf16(sacc[s2 + 1], aih, ih[g2][2], ih[g2][3]);
                }
#pragma unroll
                for (int g2 = 0; g2 < 2; g2++) {
                    const int s2 = 2 * (gp * 2 + g2);
                    mma_bf16(sacc[s2],     arl, rh[g2][0], rh[g2][1]);
                    mma_bf16(sacc[s2 + 1], arl, rh[g2][2], rh[g2][3]);
                }
#pragma unroll
                for (int g2 = 0; g2 < 2; g2++) {
                    const int s2 = 2 * (gp * 2 + g2);
                    mma_bf16(sacc[s2],     ail, ih[g2][0], ih[g2][1]);
                    mma_bf16(sacc[s2 + 1], ail, ih[g2][2], ih[g2][3]);
                }
#pragma unroll
                for (int g2 = 0; g2 < 2; g2++) {
                    const int s2 = 2 * (gp * 2 + g2);
                    mma_bf16(sacc[s2],     arh, rl[g2][0], rl[g2][1]);
                    mma_bf16(sacc[s2 + 1], arh, rl[g2][2], rl[g2][3]);
                }
#pragma unroll
                for (int g2 = 0; g2 < 2; g2++) {
                    const int s2 = 2 * (gp * 2 + g2);
                    mma_bf16(sacc[s2],     aih, il[g2][0], il[g2][1]);
                    mma_bf16(sacc[s2 + 1], aih, il[g2][2], il[g2][3]);
                }
            }
        }

        float pm0 = -INFINITY, pm1 = -INFINITY;
#pragma unroll
        for (int f = 0; f < 8; f++) {
            const int sb2 = s0 + f * 8 + (lane & 3) * 2;
            const float2 gs0 = g_gate[h * SEQ + sb2];
            const float2 gs1 = g_gate[h * SEQ + sb2 + 1];
            float v00 = sacc[f][0] * SCALE_F * (gs0.x * gt0.x + gs0.y * gt0.y);
            float v01 = sacc[f][1] * SCALE_F * (gs1.x * gt0.x + gs1.y * gt0.y);
            float v10 = sacc[f][2] * SCALE_F * (gs0.x * gt1.x + gs0.y * gt1.y);
            float v11 = sacc[f][3] * SCALE_F * (gs1.x * gt1.x + gs1.y * gt1.y);
            if (sb2 > t0g)     v00 = -INFINITY;
            if (sb2 + 1 > t0g) v01 = -INFINITY;
            if (sb2 > t1g)     v10 = -INFINITY;
            if (sb2 + 1 > t1g) v11 = -INFINITY;
            sacc[f][0] = v00; sacc[f][1] = v01; sacc[f][2] = v10; sacc[f][3] = v11;
            pm0 = fmaxf(pm0, fmaxf(v00, v01));
            pm1 = fmaxf(pm1, fmaxf(v10, v11));
        }
        pm0 = fmaxf(pm0, __shfl_xor_sync(0xffffffffu, pm0, 1));
        pm0 = fmaxf(pm0, __shfl_xor_sync(0xffffffffu, pm0, 2));
        pm1 = fmaxf(pm1, __shfl_xor_sync(0xffffffffu, pm1, 1));
        pm1 = fmaxf(pm1, __shfl_xor_sync(0xffffffffu, pm1, 2));

        const float mn0 = fmaxf(m0, pm0), mn1 = fmaxf(m1, pm1);
        const float cr0 = __expf(m0 - mn0), cr1 = __expf(m1 - mn1);
        float rs0 = 0.f, rs1 = 0.f;
#pragma unroll
        for (int f = 0; f < 8; f++) {
            sacc[f][0] = __expf(sacc[f][0] - mn0);
            sacc[f][1] = __expf(sacc[f][1] - mn0);
            sacc[f][2] = __expf(sacc[f][2] - mn1);
            sacc[f][3] = __expf(sacc[f][3] - mn1);
            rs0 += sacc[f][0] + sacc[f][1];
            rs1 += sacc[f][2] + sacc[f][3];
        }
        rs0 += __shfl_xor_sync(0xffffffffu, rs0, 1);
        rs0 += __shfl_xor_sync(0xffffffffu, rs0, 2);
        rs1 += __shfl_xor_sync(0xffffffffu, rs1, 1);
        rs1 += __shfl_xor_sync(0xffffffffu, rs1, 2);
        l0 = l0 * cr0 + rs0; m0 = mn0;
        l1 = l1 * cr1 + rs1; m1 = mn1;
#pragma unroll
        for (int f = 0; f < 8; f++) {
            oacc[f][0] *= cr0; oacc[f][1] *= cr0;
            oacc[f][2] *= cr1; oacc[f][3] *= cr1;
        }

#pragma unroll
        for (int j = 0; j < 4; j++) {
            float p00 = sacc[2 * j][0],     p01 = sacc[2 * j][1];
            float p02 = sacc[2 * j][2],     p03 = sacc[2 * j][3];
            float p10 = sacc[2 * j + 1][0], p11 = sacc[2 * j + 1][1];
            float p12 = sacc[2 * j + 1][2], p13 = sacc[2 * j + 1][3];
            float h00 = __bfloat162float(__float2bfloat16(p00));
            float h01 = __bfloat162float(__float2bfloat16(p01));
            float h02 = __bfloat162float(__float2bfloat16(p02));
            float h03 = __bfloat162float(__float2bfloat16(p03));
            float h10 = __bfloat162float(__float2bfloat16(p10));
            float h11 = __bfloat162float(__float2bfloat16(p11));
            float h12 = __bfloat162float(__float2bfloat16(p12));
            float h13 = __bfloat162float(__float2bfloat16(p13));
            uint32_t ph[4] = {pack_bf16(h00, h01), pack_bf16(h02, h03),
                              pack_bf16(h10, h11), pack_bf16(h12, h13)};
            uint32_t pl[4] = {pack_bf16(p00 - h00, p01 - h01), pack_bf16(p02 - h02, p03 - h03),
                              pack_bf16(p10 - h10, p11 - h11), pack_bf16(p12 - h12, p13 - h13)};
#pragma unroll
            for (int dgp = 0; dgp < 2; dgp++) {
                uint32_t vh[2][4], vl[2][4];
#pragma unroll
                for (int d2 = 0; d2 < 2; d2++) {
                    const int dg = dgp * 2 + d2;
                    const uint32_t offV = SWZ128((uint32_t)((16 * j + a_row) * 128) +
                                                 (uint32_t)(dg * 32) + a_cb);
                    ldsm_x4_t(vh[d2][0], vh[d2][1], vh[d2][2], vh[d2][3], vH + offV);
                    ldsm_x4_t(vl[d2][0], vl[d2][1], vl[d2][2], vl[d2][3], vL + offV);
                }
                // 3 passes x 4 independent MMAs
#pragma unroll
                for (int d2 = 0; d2 < 2; d2++) {
                    const int o2 = 2 * (dgp * 2 + d2);
                    mma_bf16(oacc[o2],     ph, vh[d2][0], vh[d2][1]);
                    mma_bf16(oacc[o2 + 1], ph, vh[d2][2], vh[d2][3]);
                }
#pragma unroll
                for (int d2 = 0; d2 < 2; d2++) {
                    const int o2 = 2 * (dgp * 2 + d2);
                    mma_bf16(oacc[o2],     pl, vh[d2][0], vh[d2][1]);
                    mma_bf16(oacc[o2 + 1], pl, vh[d2][2], vh[d2][3]);
                }
#pragma unroll
                for (int d2 = 0; d2 < 2; d2++) {
                    const int o2 = 2 * (dgp * 2 + d2);
                    mma_bf16(oacc[o2],     ph, vl[d2][0], vl[d2][1]);
                    mma_bf16(oacc[o2 + 1], ph, vl[d2][2], vl[d2][3]);
                }
            }
        }
        __syncthreads();
        if (i + 2 < nS && tid == 0) issue_kv(i + 2, i & 1);
    }

    const float iv0 = 1.0f / l0, iv1 = 1.0f / l1;
#pragma unroll
    for (int f = 0; f < 8; f++) {
        const int d = f * 8 + (lane & 3) * 2;
        float o00 = oacc[f][0] * iv0, o01 = oacc[f][1] * iv0;
        float o10 = oacc[f][2] * iv1, o11 = oacc[f][3] * iv1;
        float h00 = __bfloat162float(__float2bfloat16(o00));
        float h01 = __bfloat162float(__float2bfloat16(o01));
        float h10 = __bfloat162float(__float2bfloat16(o10));
        float h11 = __bfloat162float(__float2bfloat16(o11));
        size_t off0 = gemmA_off(b * SEQ + t0g, h * 64 + d);
        size_t off1 = gemmA_off(b * SEQ + t1g, h * 64 + d);
        *(uint32_t*)((char*)g_ah + off0) = pack_bf16(h00, h01);
        *(uint32_t*)((char*)g_al + off0) = pack_bf16(o00 - h00, o01 - h01);
        *(uint32_t*)((char*)g_ah + off1) = pack_bf16(h10, h11);
        *(uint32_t*)((char*)g_al + off1) = pack_bf16(o10 - h10, o11 - h11);
    }
}

// ---------------- launch ---------------------------------------------------
extern "C" void kernel_launch(void* const* d_in, const int* in_sizes, int n_in,
                              void* d_out, int out_size) {
    const float* x     = (const float*)d_in[0];
    const float* Wq    = (const float*)d_in[1];
    const float* Wk    = (const float*)d_in[2];
    const float* Wv    = (const float*)d_in[3];
    const float* Wo    = (const float*)d_in[4];
    const float* theta = (const float*)d_in[5];
    float* out = (float*)d_out;

    float *qraw, *kraw, *v;
    __nv_bfloat16 *xh, *xl, *ah, *al, *vh, *vl;
    __nv_bfloat16 *wqh, *wql, *wkh, *wkl, *wvh, *wvl, *woh, *wol;
    cudaGetSymbolAddress((void**)&qraw, g_qraw);
    cudaGetSymbolAddress((void**)&kraw, g_kraw);
    cudaGetSymbolAddress((void**)&v,    g_v);
    cudaGetSymbolAddress((void**)&xh,  g_xh);
    cudaGetSymbolAddress((void**)&xl,  g_xl);
    cudaGetSymbolAddress((void**)&ah,  g_ah);
    cudaGetSymbolAddress((void**)&al,  g_al);
    cudaGetSymbolAddress((void**)&vh,  g_vh);
    cudaGetSymbolAddress((void**)&vl,  g_vl);
    cudaGetSymbolAddress((void**)&wqh, g_wqh);
    cudaGetSymbolAddress((void**)&wql, g_wql);
    cudaGetSymbolAddress((void**)&wkh, g_wkh);
    cudaGetSymbolAddress((void**)&wkl, g_wkl);
    cudaGetSymbolAddress((void**)&wvh, g_wvh);
    cudaGetSymbolAddress((void**)&wvl, g_wvl);
    cudaGetSymbolAddress((void**)&woh, g_woh);
    cudaGetSymbolAddress((void**)&wol, g_wol);

    cudaFuncSetAttribute(gemm_bf16x3,
                         cudaFuncAttributeMaxDynamicSharedMemorySize, GEMM_SMEM);
    cudaFuncSetAttribute(attn_mma,
                         cudaFuncAttributeMaxDynamicSharedMemorySize, ATT_SMEM);

    dim3 tblk(32, 8);

    convert_split_gemm<<<MROWS * CDIM / 2 / 256, 256>>>(x, xh, xl);
    gate_init<<<HEADS * SEQ / 256, 256>>>(theta);

    transpose_split<<<dim3(2 * CDIM / 32, CDIM / 32), tblk>>>(Wq, wqh, wql, CDIM, 2 * CDIM);
    gemm_bf16x3<<<dim3(2 * CDIM / 256, MROWS / 128), 256, GEMM_SMEM>>>(xh, xl, wqh, wql, qraw, 2 * CDIM);
    transpose_split<<<dim3(2 * CDIM / 32, CDIM / 32), tblk>>>(Wk, wkh, wkl, CDIM, 2 * CDIM);
    gemm_bf16x3<<<dim3(2 * CDIM / 256, MROWS / 128), 256, GEMM_SMEM>>>(xh, xl, wkh, wkl, kraw, 2 * CDIM);
    transpose_split<<<dim3(CDIM / 32, CDIM / 32), tblk>>>(Wv, wvh, wvl, CDIM, CDIM);
    gemm_bf16x3<<<dim3(CDIM / 256, MROWS / 128), 256, GEMM_SMEM>>>(xh, xl, wvh, wvl, v, CDIM);

    transform_qk_bf16<<<MROWS * CDIM / 2 / 256, 256>>>();
    convert_split_att<<<MROWS * CDIM / 2 / 256, 256>>>(v, vh, vl);

    attn_mma<<<dim3(SEQ / AQT, HEADS, BATCH), 256, ATT_SMEM>>>();

    transpose_split<<<dim3(CDIM / 32, CDIM / 32), tblk>>>(Wo, woh, wol, CDIM, CDIM);
    gemm_bf16x3<<<dim3(CDIM / 256, MROWS / 128), 256, GEMM_SMEM>>>(ah, al, woh, wol, out, CDIM);
}

// round 10
// speedup vs baseline: 1.2532x; 1.1014x over previous
#include <cuda_runtime.h>
#include <cuda_bf16.h>
#include <cuda_fp16.h>
#include <cstdint>
#include <math.h>

// Problem constants
#define BATCH   2
#define SEQ     2048
#define CDIM    1024
#define HEADS   16
#define HDIM    64
#define GAMMA_F 8.0f
#define SCALE_F 0.125f
#define MROWS   (BATCH*SEQ)          // 4096
#define KDIM    1024

// ---------------- scratch (device globals; no allocation allowed) ----------
__device__ float g_qraw[MROWS * 2 * CDIM];
__device__ float g_kraw[MROWS * 2 * CDIM];
__device__ float g_v   [MROWS * CDIM];

// split-bf16 GEMM operands (pre-swizzled tile-blocked layouts)
__device__ __nv_bfloat16 g_xh [MROWS * CDIM];
__device__ __nv_bfloat16 g_xl [MROWS * CDIM];
__device__ __nv_bfloat16 g_ah [MROWS * CDIM];
__device__ __nv_bfloat16 g_al [MROWS * CDIM];
__device__ __nv_bfloat16 g_wqh[2 * CDIM * CDIM];
__device__ __nv_bfloat16 g_wql[2 * CDIM * CDIM];
__device__ __nv_bfloat16 g_wkh[2 * CDIM * CDIM];
__device__ __nv_bfloat16 g_wkl[2 * CDIM * CDIM];
__device__ __nv_bfloat16 g_wvh[CDIM * CDIM];
__device__ __nv_bfloat16 g_wvl[CDIM * CDIM];
__device__ __nv_bfloat16 g_woh[CDIM * CDIM];
__device__ __nv_bfloat16 g_wol[CDIM * CDIM];

// attention operands: Q single fp16, K fp16 hi/lo, V fp16 hi/lo
__device__ __half g_qr [MROWS * CDIM];
__device__ __half g_qi [MROWS * CDIM];
__device__ __half g_krh[MROWS * CDIM];
__device__ __half g_krl[MROWS * CDIM];
__device__ __half g_kih[MROWS * CDIM];
__device__ __half g_kil[MROWS * CDIM];
__device__ __half g_vh [MROWS * CDIM];
__device__ __half g_vl [MROWS * CDIM];
__device__ float2 g_gate[HEADS * SEQ];

// ---------------- helpers ---------------------------------------------------
__device__ __forceinline__ uint32_t smem_u32(const void* p) {
    uint32_t a;
    asm("{ .reg .u64 t; cvta.to.shared.u64 t, %1; cvt.u32.u64 %0, t; }"
        : "=r"(a) : "l"(p));
    return a;
}
#define SWZ128(o) ((o) ^ (((o) >> 3) & 0x70))

__device__ __forceinline__ size_t gemmA_off(int row, int col) {
    return ((size_t)((row >> 7) * 16 + (col >> 6)) << 14) +
           SWZ128((uint32_t)((row & 127) * 128 + (col & 63) * 2));
}
__device__ __forceinline__ size_t att_off(int b, int h, int t, int d) {
    return ((size_t)((b * HEADS + h) * 32 + (t >> 6)) << 13) +
           SWZ128((uint32_t)((t & 63) * 128 + d * 2));
}

#define MBARRIER_INIT(mbar, count) \
    asm volatile("mbarrier.init.shared.b64 [%0], %1;" :: "r"((uint32_t)(mbar)), "r"((uint32_t)(count)) : "memory")
#define MBAR_EXPECT(mbar, bytes) \
    asm volatile("mbarrier.arrive.expect_tx.shared.b64 _, [%0], %1;" :: "r"((uint32_t)(mbar)), "r"((uint32_t)(bytes)) : "memory")

#define MBARRIER_WAIT_PARITY(mbar, parity) do { \
    uint32_t _m = (uint32_t)(mbar); uint32_t _p = (uint32_t)(parity); uint32_t _d; \
    asm volatile("{\n\t.reg .pred p;\n\t" \
        "mbarrier.try_wait.parity.acquire.cta.shared::cta.b64 p, [%1], %2;\n\t" \
        "selp.b32 %0, 1, 0, p;\n\t}" : "=r"(_d) : "r"(_m), "r"(_p) : "memory"); \
    if (!_d) { \
        asm volatile("{\n\t.reg .pred P1;\n\t" \
            "WL_%=:\n\t" \
            "mbarrier.try_wait.parity.acquire.cta.shared::cta.b64 P1, [%0], %1, 0x989680;\n\t" \
            "@P1 bra.uni WD_%=;\n\tbra.uni WL_%=;\n\tWD_%=:\n\t}" \
            :: "r"(_m), "r"(_p) : "memory"); \
    } } while (0)

__device__ __forceinline__ void bulk_g2s(uint32_t dst, const void* src,
                                         uint32_t bytes, uint32_t mbar) {
    asm volatile(
        "cp.async.bulk.shared::cluster.global.mbarrier::complete_tx::bytes [%0], [%1], %2, [%3];"
        :: "r"(dst), "l"(src), "r"(bytes), "r"(mbar) : "memory");
}

__device__ __forceinline__ void ldsm_x4(uint32_t& r0, uint32_t& r1,
                                        uint32_t& r2, uint32_t& r3, uint32_t addr) {
    asm volatile("ldmatrix.sync.aligned.m8n8.x4.shared.b16 {%0,%1,%2,%3}, [%4];"
                 : "=r"(r0), "=r"(r1), "=r"(r2), "=r"(r3) : "r"(addr));
}
__device__ __forceinline__ void ldsm_x4_t(uint32_t& r0, uint32_t& r1,
                                          uint32_t& r2, uint32_t& r3, uint32_t addr) {
    asm volatile("ldmatrix.sync.aligned.m8n8.x4.trans.shared.b16 {%0,%1,%2,%3}, [%4];"
                 : "=r"(r0), "=r"(r1), "=r"(r2), "=r"(r3) : "r"(addr));
}

__device__ __forceinline__ void mma_bf16(float* c, const uint32_t* a,
                                         uint32_t b0, uint32_t b1) {
    asm volatile(
        "mma.sync.aligned.m16n8k16.row.col.f32.bf16.bf16.f32 "
        "{%0,%1,%2,%3}, {%4,%5,%6,%7}, {%8,%9}, {%0,%1,%2,%3};"
        : "+f"(c[0]), "+f"(c[1]), "+f"(c[2]), "+f"(c[3])
        : "r"(a[0]), "r"(a[1]), "r"(a[2]), "r"(a[3]), "r"(b0), "r"(b1));
}
__device__ __forceinline__ void mma_fp16(float* c, const uint32_t* a,
                                         uint32_t b0, uint32_t b1) {
    asm volatile(
        "mma.sync.aligned.m16n8k16.row.col.f32.f16.f16.f32 "
        "{%0,%1,%2,%3}, {%4,%5,%6,%7}, {%8,%9}, {%0,%1,%2,%3};"
        : "+f"(c[0]), "+f"(c[1]), "+f"(c[2]), "+f"(c[3])
        : "r"(a[0]), "r"(a[1]), "r"(a[2]), "r"(a[3]), "r"(b0), "r"(b1));
}

__device__ __forceinline__ uint32_t pack_bf16(float a, float b) {
    __nv_bfloat162 t = __float22bfloat162_rn(make_float2(a, b));
    return *reinterpret_cast<uint32_t*>(&t);
}
__device__ __forceinline__ uint32_t pack_half(float a, float b) {
    __half2 t = __floats2half2_rn(a, b);
    return *reinterpret_cast<uint32_t*>(&t);
}

// ---------------- split-bf16 GEMM mainloop (128x256, 8 warps, pass-major) ---
#define BK       64
#define NCH      (KDIM / BK)
#define A_TB     16384
#define B_TB     32768
#define STG_B    (2 * A_TB + 2 * B_TB)   // 98304
#define GEMM_SMEM (1024 + 2 * STG_B)     // 197632

__device__ __forceinline__ void gemm_body(
    const char* cAh, const char* cAl, const char* cBh, const char* cBl,
    int mb, int nb, float acc[4][8][4]) {
    extern __shared__ char smem[];
    const uint32_t sb = smem_u32(smem);
    const int tid = threadIdx.x, wid = tid >> 5, lane = tid & 31;
    const int wm = (wid & 1) * 64;
    const int wn = (wid >> 1) * 64;

    const size_t mbB = ((size_t)mb * 16) << 14;
    const size_t nbB0 = ((size_t)(nb * 2) * 16) << 14;
    const size_t nbB1 = ((size_t)(nb * 2 + 1) * 16) << 14;

    if (tid == 0) { MBARRIER_INIT(sb, 1); MBARRIER_INIT(sb + 8, 1); }
    __syncthreads();

    auto issue = [&](int chunk, int buf) {
        const uint32_t st = sb + 1024 + buf * STG_B;
        const uint32_t bar = sb + buf * 8;
        const size_t kB = ((size_t)chunk) << 14;
        MBAR_EXPECT(bar, STG_B);
        bulk_g2s(st,             cAh + mbB + kB,  A_TB, bar);
        bulk_g2s(st + A_TB,      cAl + mbB + kB,  A_TB, bar);
        bulk_g2s(st + 2 * A_TB,          cBh + nbB0 + kB, A_TB, bar);
        bulk_g2s(st + 2 * A_TB + A_TB,   cBh + nbB1 + kB, A_TB, bar);
        bulk_g2s(st + 2 * A_TB + B_TB,        cBl + nbB0 + kB, A_TB, bar);
        bulk_g2s(st + 2 * A_TB + B_TB + A_TB, cBl + nbB1 + kB, A_TB, bar);
    };

    if (tid == 0) { issue(0, 0); issue(1, 1); }

#pragma unroll
    for (int i = 0; i < 4; i++)
#pragma unroll
        for (int j = 0; j < 8; j++)
#pragma unroll
            for (int e = 0; e < 4; e++) acc[i][j][e] = 0.f;

    const int a_row = (lane & 15);
    const uint32_t a_cb = (uint32_t)((lane >> 4) * 16);
    const int b_row = ((lane >> 4) & 1) * 8 + (lane & 7);
    const uint32_t b_cb = (uint32_t)(((lane >> 3) & 1) * 16);

    for (int i = 0; i < NCH; i++) {
        MBARRIER_WAIT_PARITY(sb + (i & 1) * 8, (i >> 1) & 1);

        const uint32_t st = sb + 1024 + (i & 1) * STG_B;
        const uint32_t aH = st, aL = st + A_TB;
        const uint32_t bH = st + 2 * A_TB, bL = st + 2 * A_TB + B_TB;

#pragma unroll
        for (int ks = 0; ks < 4; ks++) {
            const uint32_t kb = (uint32_t)(ks * 32);
            uint32_t ah[4][4], al[4][4];
#pragma unroll
            for (int mi = 0; mi < 4; mi++) {
                uint32_t off = SWZ128((uint32_t)((wm + mi * 16 + a_row) * 128) + kb + a_cb);
                ldsm_x4(ah[mi][0], ah[mi][1], ah[mi][2], ah[mi][3], aH + off);
                ldsm_x4(al[mi][0], al[mi][1], al[mi][2], al[mi][3], aL + off);
            }
#pragma unroll
            for (int hb = 0; hb < 2; hb++) {
                uint32_t bh[2][4], bl[2][4];
#pragma unroll
                for (int g2 = 0; g2 < 2; g2++) {
                    const int ng = hb * 2 + g2;
                    uint32_t off = SWZ128((uint32_t)((wn + ng * 16 + b_row) * 128) + kb + b_cb);
                    ldsm_x4(bh[g2][0], bh[g2][1], bh[g2][2], bh[g2][3], bH + off);
                    ldsm_x4(bl[g2][0], bl[g2][1], bl[g2][2], bl[g2][3], bL + off);
                }
#pragma unroll
                for (int g2 = 0; g2 < 2; g2++)
#pragma unroll
                    for (int mi = 0; mi < 4; mi++) {
                        const int nj = 2 * (hb * 2 + g2);
                        mma_bf16(acc[mi][nj],     ah[mi], bh[g2][0], bh[g2][1]);
                        mma_bf16(acc[mi][nj + 1], ah[mi], bh[g2][2], bh[g2][3]);
                    }
#pragma unroll
                for (int g2 = 0; g2 < 2; g2++)
#pragma unroll
                    for (int mi = 0; mi < 4; mi++) {
                        const int nj = 2 * (hb * 2 + g2);
                        mma_bf16(acc[mi][nj],     ah[mi], bl[g2][0], bl[g2][1]);
                        mma_bf16(acc[mi][nj + 1], ah[mi], bl[g2][2], bl[g2][3]);
                    }
#pragma unroll
                for (int g2 = 0; g2 < 2; g2++)
#pragma unroll
                    for (int mi = 0; mi < 4; mi++) {
                        const int nj = 2 * (hb * 2 + g2);
                        mma_bf16(acc[mi][nj],     al[mi], bh[g2][0], bh[g2][1]);
                        mma_bf16(acc[mi][nj + 1], al[mi], bh[g2][2], bh[g2][3]);
                    }
            }
        }
        __syncthreads();
        if (i + 2 < NCH && tid == 0) issue(i + 2, i & 1);
    }
}

__device__ __forceinline__ void gemm_store(float acc[4][8][4], float* Cm, int N,
                                           int m0, int n0) {
    const int tid = threadIdx.x, wid = tid >> 5, lane = tid & 31;
    const int wm = (wid & 1) * 64, wn = (wid >> 1) * 64;
    const int cr = lane >> 2;
    const int cc = (lane & 3) * 2;
#pragma unroll
    for (int mi = 0; mi < 4; mi++) {
#pragma unroll
        for (int nj = 0; nj < 8; nj++) {
            const int r = m0 + wm + mi * 16 + cr;
            const int c = n0 + wn + nj * 8 + cc;
            *(float2*)&Cm[(size_t)r * N + c] = make_float2(acc[mi][nj][0], acc[mi][nj][1]);
            *(float2*)&Cm[(size_t)(r + 8) * N + c] = make_float2(acc[mi][nj][2], acc[mi][nj][3]);
        }
    }
}

// Combined Q/K/V projection GEMM: grid.x = 20 (8 Q | 8 K | 4 V), grid.y = 32
__global__ __launch_bounds__(256, 1)
void gemm_qkv(const __nv_bfloat16* __restrict__ xh, const __nv_bfloat16* __restrict__ xl,
              const __nv_bfloat16* __restrict__ wqh, const __nv_bfloat16* __restrict__ wql,
              const __nv_bfloat16* __restrict__ wkh, const __nv_bfloat16* __restrict__ wkl,
              const __nv_bfloat16* __restrict__ wvh, const __nv_bfloat16* __restrict__ wvl,
              float* __restrict__ qraw, float* __restrict__ kraw, float* __restrict__ vout) {
    const int nx = blockIdx.x;
    const __nv_bfloat16 *Bh, *Bl;
    float* Cm;
    int N, nb;
    if (nx < 8)       { Bh = wqh; Bl = wql; Cm = qraw; N = 2 * CDIM; nb = nx; }
    else if (nx < 16) { Bh = wkh; Bl = wkl; Cm = kraw; N = 2 * CDIM; nb = nx - 8; }
    else              { Bh = wvh; Bl = wvl; Cm = vout; N = CDIM;     nb = nx - 16; }

    float acc[4][8][4];
    gemm_body((const char*)xh, (const char*)xl, (const char*)Bh, (const char*)Bl,
              blockIdx.y, nb, acc);
    gemm_store(acc, Cm, N, blockIdx.y * 128, nb * 256);
}

// Output projection GEMM
__global__ __launch_bounds__(256, 1)
void gemm_bf16x3(const __nv_bfloat16* __restrict__ Ah, const __nv_bfloat16* __restrict__ Al,
                 const __nv_bfloat16* __restrict__ Bh, const __nv_bfloat16* __restrict__ Bl,
                 float* __restrict__ Cm, int N) {
    float acc[4][8][4];
    gemm_body((const char*)Ah, (const char*)Al, (const char*)Bh, (const char*)Bl,
              blockIdx.y, blockIdx.x, acc);
    gemm_store(acc, Cm, N, blockIdx.y * 128, blockIdx.x * 256);
}

// ---------------- fp32 -> (hi,lo) bf16 split, GEMM-A tiled layout ----------
__global__ __launch_bounds__(256)
void convert_split_gemm(const float* __restrict__ src, __nv_bfloat16* __restrict__ hi,
                        __nv_bfloat16* __restrict__ lo) {
    int i2 = blockIdx.x * 256 + threadIdx.x;
    int row = i2 >> 9, col = (i2 & 511) * 2;
    float2 v = *(const float2*)&src[(size_t)row * CDIM + col];
    __nv_bfloat16 h0 = __float2bfloat16(v.x), h1 = __float2bfloat16(v.y);
    size_t off = gemmA_off(row, col);
    *(uint32_t*)((char*)hi + off) = pack_bf16(__bfloat162float(h0), __bfloat162float(h1));
    *(uint32_t*)((char*)lo + off) = pack_bf16(v.x - __bfloat162float(h0),
                                              v.y - __bfloat162float(h1));
}

// fp32 -> fp16 hi/lo in ATTENTION tiled layout (for V)
__global__ __launch_bounds__(256)
void convert_split_att(const float* __restrict__ src, __half* __restrict__ hi,
                       __half* __restrict__ lo) {
    int i2 = blockIdx.x * 256 + threadIdx.x;
    int bt = i2 >> 9, col = (i2 & 511) * 2;
    int b = bt >> 11, t = bt & (SEQ - 1);
    int h = col >> 6, d = col & 63;
    float2 v = *(const float2*)&src[(size_t)bt * CDIM + col];
    float h0 = __half2float(__float2half(v.x));
    float h1 = __half2float(__float2half(v.y));
    size_t off = att_off(b, h, t, d);
    *(uint32_t*)((char*)hi + off) = pack_half(h0, h1);
    *(uint32_t*)((char*)lo + off) = pack_half(v.x - h0, v.y - h1);
}

// ---------------- weight transpose + split -> GEMM-A tiled layout ----------
__global__ __launch_bounds__(256)
void transpose_split(const float* __restrict__ W, __nv_bfloat16* __restrict__ Hh,
                     __nv_bfloat16* __restrict__ Hl, int K, int N) {
    __shared__ float t[32][33];
    const int tx = threadIdx.x, ty = threadIdx.y;
    const int n0 = blockIdx.x * 32, k0 = blockIdx.y * 32;
#pragma unroll
    for (int i = 0; i < 32; i += 8)
        t[ty + i][tx] = W[(size_t)(k0 + ty + i) * N + n0 + tx];
    __syncthreads();
#pragma unroll
    for (int i = 0; i < 32; i += 8) {
        float v = t[tx][ty + i];
        __nv_bfloat16 h = __float2bfloat16(v);
        size_t off = gemmA_off(n0 + ty + i, k0 + tx);
        *(__nv_bfloat16*)((char*)Hh + off) = h;
        *(__nv_bfloat16*)((char*)Hl + off) = __float2bfloat16(v - __bfloat162float(h));
    }
}

// ---------------- amp/phase transform -> fp16 (Q single, K hi/lo) ----------
__device__ __forceinline__ float softplus_f(float a) {
    return (a > 20.f) ? a : log1pf(expf(a));
}

__global__ __launch_bounds__(256)
void transform_qk_fp16() {
    int i2 = blockIdx.x * 256 + threadIdx.x;
    int c2 = i2 * 2;
    int bt = c2 >> 10;
    int c  = c2 & 1023;
    int b = bt >> 11, t = bt & (SEQ - 1);
    int h = c >> 6, d = c & 63;
    size_t rbase = (size_t)bt * (2 * CDIM);
    size_t off = att_off(b, h, t, d);

    float qa0 = g_qraw[rbase + c],        qa1 = g_qraw[rbase + c + 1];
    float qp0 = g_qraw[rbase + CDIM + c], qp1 = g_qraw[rbase + CDIM + c + 1];
    float ka0 = g_kraw[rbase + c],        ka1 = g_kraw[rbase + c + 1];
    float kp0 = g_kraw[rbase + CDIM + c], kp1 = g_kraw[rbase + CDIM + c + 1];

    float qs0 = softplus_f(qa0), qs1 = softplus_f(qa1);
    float ks0 = softplus_f(ka0), ks1 = softplus_f(ka1);
    float s0, c0, s1, c1, s2, c2f, s3, c3;
    sincosf(qp0, &s0, &c0); sincosf(qp1, &s1, &c1);
    sincosf(kp0, &s2, &c2f); sincosf(kp1, &s3, &c3);

    *(uint32_t*)((char*)g_qr + off) = pack_half(qs0 * c0, qs1 * c1);
    *(uint32_t*)((char*)g_qi + off) = pack_half(qs0 * s0, qs1 * s1);

    float kr0 = ks0 * c2f, kr1 = ks1 * c3;
    float ki0 = ks0 * s2,  ki1 = ks1 * s3;
    float krh0 = __half2float(__float2half(kr0)), krh1 = __half2float(__float2half(kr1));
    float kih0 = __half2float(__float2half(ki0)), kih1 = __half2float(__float2half(ki1));
    *(uint32_t*)((char*)g_krh + off) = pack_half(krh0, krh1);
    *(uint32_t*)((char*)g_krl + off) = pack_half(kr0 - krh0, kr1 - krh1);
    *(uint32_t*)((char*)g_kih + off) = pack_half(kih0, kih1);
    *(uint32_t*)((char*)g_kil + off) = pack_half(ki0 - kih0, ki1 - kih1);
}

__global__ void gate_init(const float* __restrict__ theta) {
    int i = blockIdx.x * 256 + threadIdx.x;
    int h = i >> 11, s = i & (SEQ - 1);
    float th = theta[h] * (1.0f / GAMMA_F);
    float sn, cs;
    sincosf(th * (float)s, &sn, &cs);
    g_gate[i] = make_float2(cs, sn);
}

// ---------------- fp16 tensor-core flash attention with moiré gate ----------
#define AQT 128
#define AST 64
#define AQ_TILE 16384
#define AKV_TILE 8192
#define AKV_BUF (6 * AKV_TILE)              // 49152
#define AKV_STAGES 3
#define ATT_SMEM (1024 + 2 * AQ_TILE + AKV_STAGES * AKV_BUF)  // 181248

__global__ __launch_bounds__(256)
void attn_mma() {
    extern __shared__ char smem[];
    const uint32_t sb = smem_u32(smem);
    const uint32_t sQ  = sb + 1024;
    const uint32_t sKV = sQ + 2 * AQ_TILE;

    const int tid = threadIdx.x, w = tid >> 5, lane = tid & 31;
    const int q0 = (int)(gridDim.x - 1 - blockIdx.x) * AQT;
    const int h = blockIdx.y, b = blockIdx.z;
    const int nS = q0 / AST + 2;

    const size_t bhB = ((size_t)((b * HEADS + h) * 32)) << 13;

    if (tid == 0) {
        MBARRIER_INIT(sb, 1);
        MBARRIER_INIT(sb + 8, 1);
        MBARRIER_INIT(sb + 16, 1);
        MBARRIER_INIT(sb + 24, 1);
    }
    __syncthreads();

    auto issue_kv = [&](int chunk, int buf) {
        const uint32_t st = sKV + buf * AKV_BUF;
        const uint32_t bar = sb + 8 + buf * 8;
        const size_t src = bhB + (((size_t)chunk) << 13);
        MBAR_EXPECT(bar, AKV_BUF);
        bulk_g2s(st,                (const char*)g_krh + src, AKV_TILE, bar);
        bulk_g2s(st + AKV_TILE,     (const char*)g_krl + src, AKV_TILE, bar);
        bulk_g2s(st + 2 * AKV_TILE, (const char*)g_kih + src, AKV_TILE, bar);
        bulk_g2s(st + 3 * AKV_TILE, (const char*)g_kil + src, AKV_TILE, bar);
        bulk_g2s(st + 4 * AKV_TILE, (const char*)g_vh  + src, AKV_TILE, bar);
        bulk_g2s(st + 5 * AKV_TILE, (const char*)g_vl  + src, AKV_TILE, bar);
    };

    if (tid == 0) {
        const size_t qsrc = bhB + (((size_t)(q0 >> 6)) << 13);
        MBAR_EXPECT(sb, 2 * AQ_TILE);
        bulk_g2s(sQ,           (const char*)g_qr + qsrc, AQ_TILE, sb);
        bulk_g2s(sQ + AQ_TILE, (const char*)g_qi + qsrc, AQ_TILE, sb);
#pragma unroll
        for (int c = 0; c < AKV_STAGES; c++)
            if (c < nS) issue_kv(c, c);
    }

    const int a_row = lane & 15;
    const uint32_t a_cb = (uint32_t)((lane >> 4) * 16);
    const int b_row = ((lane >> 4) & 1) * 8 + (lane & 7);
    const uint32_t b_cb = (uint32_t)(((lane >> 3) & 1) * 16);

    const int t0g = q0 + w * 16 + (lane >> 2);
    const int t1g = t0g + 8;
    const float2 gt0 = g_gate[h * SEQ + t0g];
    const float2 gt1 = g_gate[h * SEQ + t1g];

    float m0 = -INFINITY, m1 = -INFINITY, l0 = 0.f, l1 = 0.f;
    float oacc[8][4];
#pragma unroll
    for (int f = 0; f < 8; f++)
#pragma unroll
        for (int e = 0; e < 4; e++) oacc[f][e] = 0.f;

    MBARRIER_WAIT_PARITY(sb, 0);

    for (int i = 0; i < nS; i++) {
        const int stg = i % AKV_STAGES;
        MBARRIER_WAIT_PARITY(sb + 8 + stg * 8, (i / AKV_STAGES) & 1);

        const int s0 = i * AST;
        const uint32_t kb0 = sKV + stg * AKV_BUF;
        const uint32_t kRH = kb0, kRL = kb0 + AKV_TILE;
        const uint32_t kIH = kb0 + 2 * AKV_TILE, kIL = kb0 + 3 * AKV_TILE;
        const uint32_t vH = kb0 + 4 * AKV_TILE, vL = kb0 + 5 * AKV_TILE;

        float sacc[8][4];
#pragma unroll
        for (int f = 0; f < 8; f++)
#pragma unroll
            for (int e = 0; e < 4; e++) sacc[f][e] = 0.f;

#pragma unroll
        for (int jd = 0; jd < 4; jd++) {
            const uint32_t kb = (uint32_t)(jd * 32);
            const uint32_t offA = SWZ128((uint32_t)((w * 16 + a_row) * 128) + kb + a_cb);
            uint32_t aqr[4], aqi[4];
            ldsm_x4(aqr[0], aqr[1], aqr[2], aqr[3], sQ + offA);
            ldsm_x4(aqi[0], aqi[1], aqi[2], aqi[3], sQ + AQ_TILE + offA);
#pragma unroll
            for (int gp = 0; gp < 2; gp++) {
                uint32_t rh[2][4], rl[2][4], ih[2][4], il[2][4];
#pragma unroll
                for (int g2 = 0; g2 < 2; g2++) {
                    const int g = gp * 2 + g2;
                    const uint32_t offB = SWZ128((uint32_t)((g * 16 + b_row) * 128) + kb + b_cb);
                    ldsm_x4(rh[g2][0], rh[g2][1], rh[g2][2], rh[g2][3], kRH + offB);
                    ldsm_x4(rl[g2][0], rl[g2][1], rl[g2][2], rl[g2][3], kRL + offB);
                    ldsm_x4(ih[g2][0], ih[g2][1], ih[g2][2], ih[g2][3], kIH + offB);
                    ldsm_x4(il[g2][0], il[g2][1], il[g2][2], il[g2][3], kIL + offB);
                }
#pragma unroll
                for (int g2 = 0; g2 < 2; g2++) {
                    const int s2 = 2 * (gp * 2 + g2);
                    mma_fp16(sacc[s2],     aqr, rh[g2][0], rh[g2][1]);
                    mma_fp16(sacc[s2 + 1], aqr, rh[g2][2], rh[g2][3]);
                }
#pragma unroll
                for (int g2 = 0; g2 < 2; g2++) {
                    const int s2 = 2 * (gp * 2 + g2);
                    mma_fp16(sacc[s2],     aqi, ih[g2][0], ih[g2][1]);
                    mma_fp16(sacc[s2 + 1], aqi, ih[g2][2], ih[g2][3]);
                }
#pragma unroll
                for (int g2 = 0; g2 < 2; g2++) {
                    const int s2 = 2 * (gp * 2 + g2);
                    mma_fp16(sacc[s2],     aqr, rl[g2][0], rl[g2][1]);
                    mma_fp16(sacc[s2 + 1], aqr, rl[g2][2], rl[g2][3]);
                }
#pragma unroll
                for (int g2 = 0; g2 < 2; g2++) {
                    const int s2 = 2 * (gp * 2 + g2);
                    mma_fp16(sacc[s2],     aqi, il[g2][0], il[g2][1]);
                    mma_fp16(sacc[s2 + 1], aqi, il[g2][2], il[g2][3]);
                }
            }
        }

        float pm0 = -INFINITY, pm1 = -INFINITY;
#pragma unroll
        for (int f = 0; f < 8; f++) {
            const int sb2 = s0 + f * 8 + (lane & 3) * 2;
            const float2 gs0 = g_gate[h * SEQ + sb2];
            const float2 gs1 = g_gate[h * SEQ + sb2 + 1];
            float v00 = sacc[f][0] * SCALE_F * (gs0.x * gt0.x + gs0.y * gt0.y);
            float v01 = sacc[f][1] * SCALE_F * (gs1.x * gt0.x + gs1.y * gt0.y);
            float v10 = sacc[f][2] * SCALE_F * (gs0.x * gt1.x + gs0.y * gt1.y);
            float v11 = sacc[f][3] * SCALE_F * (gs1.x * gt1.x + gs1.y * gt1.y);
            if (sb2 > t0g)     v00 = -INFINITY;
            if (sb2 + 1 > t0g) v01 = -INFINITY;
            if (sb2 > t1g)     v10 = -INFINITY;
            if (sb2 + 1 > t1g) v11 = -INFINITY;
            sacc[f][0] = v00; sacc[f][1] = v01; sacc[f][2] = v10; sacc[f][3] = v11;
            pm0 = fmaxf(pm0, fmaxf(v00, v01));
            pm1 = fmaxf(pm1, fmaxf(v10, v11));
        }
        pm0 = fmaxf(pm0, __shfl_xor_sync(0xffffffffu, pm0, 1));
        pm0 = fmaxf(pm0, __shfl_xor_sync(0xffffffffu, pm0, 2));
        pm1 = fmaxf(pm1, __shfl_xor_sync(0xffffffffu, pm1, 1));
        pm1 = fmaxf(pm1, __shfl_xor_sync(0xffffffffu, pm1, 2));

        const float mn0 = fmaxf(m0, pm0), mn1 = fmaxf(m1, pm1);
        const float cr0 = __expf(m0 - mn0), cr1 = __expf(m1 - mn1);
        float rs0 = 0.f, rs1 = 0.f;
#pragma unroll
        for (int f = 0; f < 8; f++) {
            sacc[f][0] = __expf(sacc[f][0] - mn0);
            sacc[f][1] = __expf(sacc[f][1] - mn0);
            sacc[f][2] = __expf(sacc[f][2] - mn1);
            sacc[f][3] = __expf(sacc[f][3] - mn1);
            rs0 += sacc[f][0] + sacc[f][1];
            rs1 += sacc[f][2] + sacc[f][3];
        }
        rs0 += __shfl_xor_sync(0xffffffffu, rs0, 1);
        rs0 += __shfl_xor_sync(0xffffffffu, rs0, 2);
        rs1 += __shfl_xor_sync(0xffffffffu, rs1, 1);
        rs1 += __shfl_xor_sync(0xffffffffu, rs1, 2);
        l0 = l0 * cr0 + rs0; m0 = mn0;
        l1 = l1 * cr1 + rs1; m1 = mn1;
#pragma unroll
        for (int f = 0; f < 8; f++) {
            oacc[f][0] *= cr0; oacc[f][1] *= cr0;
            oacc[f][2] *= cr1; oacc[f][3] *= cr1;
        }

#pragma unroll
        for (int j = 0; j < 4; j++) {
            uint32_t ph[4] = {
                pack_half(sacc[2 * j][0],     sacc[2 * j][1]),
                pack_half(sacc[2 * j][2],     sacc[2 * j][3]),
                pack_half(sacc[2 * j + 1][0], sacc[2 * j + 1][1]),
                pack_half(sacc[2 * j + 1][2], sacc[2 * j + 1][3])};
#pragma unroll
            for (int dgp = 0; dgp < 2; dgp++) {
                uint32_t vh[2][4], vl[2][4];
#pragma unroll
                for (int d2 = 0; d2 < 2; d2++) {
                    const int dg = dgp * 2 + d2;
                    const uint32_t offV = SWZ128((uint32_t)((16 * j + a_row) * 128) +
                                                 (uint32_t)(dg * 32) + a_cb);
                    ldsm_x4_t(vh[d2][0], vh[d2][1], vh[d2][2], vh[d2][3], vH + offV);
                    ldsm_x4_t(vl[d2][0], vl[d2][1], vl[d2][2], vl[d2][3], vL + offV);
                }
#pragma unroll
                for (int d2 = 0; d2 < 2; d2++) {
                    const int o2 = 2 * (dgp * 2 + d2);
                    mma_fp16(oacc[o2],     ph, vh[d2][0], vh[d2][1]);
                    mma_fp16(oacc[o2 + 1], ph, vh[d2][2], vh[d2][3]);
                }
#pragma unroll
                for (int d2 = 0; d2 < 2; d2++) {
                    const int o2 = 2 * (dgp * 2 + d2);
                    mma_fp16(oacc[o2],     ph, vl[d2][0], vl[d2][1]);
                    mma_fp16(oacc[o2 + 1], ph, vl[d2][2], vl[d2][3]);
                }
            }
        }
        __syncthreads();
        if (i + AKV_STAGES < nS && tid == 0) issue_kv(i + AKV_STAGES, stg);
    }

    const float iv0 = 1.0f / l0, iv1 = 1.0f / l1;
#pragma unroll
    for (int f = 0; f < 8; f++) {
        const int d = f * 8 + (lane & 3) * 2;
        float o00 = oacc[f][0] * iv0, o01 = oacc[f][1] * iv0;
        float o10 = oacc[f][2] * iv1, o11 = oacc[f][3] * iv1;
        float h00 = __bfloat162float(__float2bfloat16(o00));
        float h01 = __bfloat162float(__float2bfloat16(o01));
        float h10 = __bfloat162float(__float2bfloat16(o10));
        float h11 = __bfloat162float(__float2bfloat16(o11));
        size_t off0 = gemmA_off(b * SEQ + t0g, h * 64 + d);
        size_t off1 = gemmA_off(b * SEQ + t1g, h * 64 + d);
        *(uint32_t*)((char*)g_ah + off0) = pack_bf16(h00, h01);
        *(uint32_t*)((char*)g_al + off0) = pack_bf16(o00 - h00, o01 - h01);
        *(uint32_t*)((char*)g_ah + off1) = pack_bf16(h10, h11);
        *(uint32_t*)((char*)g_al + off1) = pack_bf16(o10 - h10, o11 - h11);
    }
}

// ---------------- launch ---------------------------------------------------
extern "C" void kernel_launch(void* const* d_in, const int* in_sizes, int n_in,
                              void* d_out, int out_size) {
    const float* x     = (const float*)d_in[0];
    const float* Wq    = (const float*)d_in[1];
    const float* Wk    = (const float*)d_in[2];
    const float* Wv    = (const float*)d_in[3];
    const float* Wo    = (const float*)d_in[4];
    const float* theta = (const float*)d_in[5];
    float* out = (float*)d_out;

    float *qraw, *kraw, *v;
    __nv_bfloat16 *xh, *xl, *ah, *al;
    __nv_bfloat16 *wqh, *wql, *wkh, *wkl, *wvh, *wvl, *woh, *wol;
    __half *vh, *vl;
    cudaGetSymbolAddress((void**)&qraw, g_qraw);
    cudaGetSymbolAddress((void**)&kraw, g_kraw);
    cudaGetSymbolAddress((void**)&v,    g_v);
    cudaGetSymbolAddress((void**)&xh,  g_xh);
    cudaGetSymbolAddress((void**)&xl,  g_xl);
    cudaGetSymbolAddress((void**)&ah,  g_ah);
    cudaGetSymbolAddress((void**)&al,  g_al);
    cudaGetSymbolAddress((void**)&vh,  g_vh);
    cudaGetSymbolAddress((void**)&vl,  g_vl);
    cudaGetSymbolAddress((void**)&wqh, g_wqh);
    cudaGetSymbolAddress((void**)&wql, g_wql);
    cudaGetSymbolAddress((void**)&wkh, g_wkh);
    cudaGetSymbolAddress((void**)&wkl, g_wkl);
    cudaGetSymbolAddress((void**)&wvh, g_wvh);
    cudaGetSymbolAddress((void**)&wvl, g_wvl);
    cudaGetSymbolAddress((void**)&woh, g_woh);
    cudaGetSymbolAddress((void**)&wol, g_wol);

    cudaFuncSetAttribute(gemm_qkv,
                         cudaFuncAttributeMaxDynamicSharedMemorySize, GEMM_SMEM);
    cudaFuncSetAttribute(gemm_bf16x3,
                         cudaFuncAttributeMaxDynamicSharedMemorySize, GEMM_SMEM);
    cudaFuncSetAttribute(attn_mma,
                         cudaFuncAttributeMaxDynamicSharedMemorySize, ATT_SMEM);

    dim3 tblk(32, 8);

    convert_split_gemm<<<MROWS * CDIM / 2 / 256, 256>>>(x, xh, xl);
    gate_init<<<HEADS * SEQ / 256, 256>>>(theta);
    transpose_split<<<dim3(2 * CDIM / 32, CDIM / 32), tblk>>>(Wq, wqh, wql, CDIM, 2 * CDIM);
    transpose_split<<<dim3(2 * CDIM / 32, CDIM / 32), tblk>>>(Wk, wkh, wkl, CDIM, 2 * CDIM);
    transpose_split<<<dim3(CDIM / 32, CDIM / 32), tblk>>>(Wv, wvh, wvl, CDIM, CDIM);
    transpose_split<<<dim3(CDIM / 32, CDIM / 32), tblk>>>(Wo, woh, wol, CDIM, CDIM);

    gemm_qkv<<<dim3(20, MROWS / 128), 256, GEMM_SMEM>>>(
        xh, xl, wqh, wql, wkh, wkl, wvh, wvl, qraw, kraw, v);

    transform_qk_fp16<<<MROWS * CDIM / 2 / 256, 256>>>();
    convert_split_att<<<MROWS * CDIM / 2 / 256, 256>>>(v, vh, vl);

    attn_mma<<<dim3(SEQ / AQT, HEADS, BATCH), 256, ATT_SMEM>>>();

    gemm_bf16x3<<<dim3(CDIM / 256, MROWS / 128), 256, GEMM_SMEM>>>(ah, al, woh, wol, out, CDIM);
}

// round 11
// speedup vs baseline: 1.5100x; 1.2049x over previous
#include <cuda_runtime.h>
#include <cuda_bf16.h>
#include <cuda_fp16.h>
#include <cstdint>
#include <math.h>

// Problem constants
#define BATCH   2
#define SEQ     2048
#define CDIM    1024
#define HEADS   16
#define HDIM    64
#define GAMMA_F 8.0f
#define SCALE_F 0.125f
#define MROWS   (BATCH*SEQ)          // 4096
#define KDIM    1024

// ---------------- scratch (device globals; no allocation allowed) ----------
__device__ float g_qraw[MROWS * 2 * CDIM];
__device__ float g_kraw[MROWS * 2 * CDIM];
__device__ float g_v   [MROWS * CDIM];

// fp16 GEMM operands (pre-swizzled tile-blocked layouts)
// A-side: exact hi/lo split. B-side (weights): single fp16.
__device__ __half g_xh [MROWS * CDIM];
__device__ __half g_xl [MROWS * CDIM];
__device__ __half g_ah [MROWS * CDIM];
__device__ __half g_al [MROWS * CDIM];
__device__ __half g_wq [2 * CDIM * CDIM];
__device__ __half g_wk [2 * CDIM * CDIM];
__device__ __half g_wv [CDIM * CDIM];
__device__ __half g_wo [CDIM * CDIM];

// attention operands: Q single fp16, K fp16 hi/lo, V fp16 hi/lo
__device__ __half g_qr [MROWS * CDIM];
__device__ __half g_qi [MROWS * CDIM];
__device__ __half g_krh[MROWS * CDIM];
__device__ __half g_krl[MROWS * CDIM];
__device__ __half g_kih[MROWS * CDIM];
__device__ __half g_kil[MROWS * CDIM];
__device__ __half g_vh [MROWS * CDIM];
__device__ __half g_vl [MROWS * CDIM];
__device__ float2 g_gate[HEADS * SEQ];

// ---------------- helpers ---------------------------------------------------
__device__ __forceinline__ uint32_t smem_u32(const void* p) {
    uint32_t a;
    asm("{ .reg .u64 t; cvta.to.shared.u64 t, %1; cvt.u32.u64 %0, t; }"
        : "=r"(a) : "l"(p));
    return a;
}
#define SWZ128(o) ((o) ^ (((o) >> 3) & 0x70))

__device__ __forceinline__ size_t gemmA_off(int row, int col) {
    return ((size_t)((row >> 7) * 16 + (col >> 6)) << 14) +
           SWZ128((uint32_t)((row & 127) * 128 + (col & 63) * 2));
}
__device__ __forceinline__ size_t att_off(int b, int h, int t, int d) {
    return ((size_t)((b * HEADS + h) * 32 + (t >> 6)) << 13) +
           SWZ128((uint32_t)((t & 63) * 128 + d * 2));
}

#define MBARRIER_INIT(mbar, count) \
    asm volatile("mbarrier.init.shared.b64 [%0], %1;" :: "r"((uint32_t)(mbar)), "r"((uint32_t)(count)) : "memory")
#define MBAR_EXPECT(mbar, bytes) \
    asm volatile("mbarrier.arrive.expect_tx.shared.b64 _, [%0], %1;" :: "r"((uint32_t)(mbar)), "r"((uint32_t)(bytes)) : "memory")

#define MBARRIER_WAIT_PARITY(mbar, parity) do { \
    uint32_t _m = (uint32_t)(mbar); uint32_t _p = (uint32_t)(parity); uint32_t _d; \
    asm volatile("{\n\t.reg .pred p;\n\t" \
        "mbarrier.try_wait.parity.acquire.cta.shared::cta.b64 p, [%1], %2;\n\t" \
        "selp.b32 %0, 1, 0, p;\n\t}" : "=r"(_d) : "r"(_m), "r"(_p) : "memory"); \
    if (!_d) { \
        asm volatile("{\n\t.reg .pred P1;\n\t" \
            "WL_%=:\n\t" \
            "mbarrier.try_wait.parity.acquire.cta.shared::cta.b64 P1, [%0], %1, 0x989680;\n\t" \
            "@P1 bra.uni WD_%=;\n\tbra.uni WL_%=;\n\tWD_%=:\n\t}" \
            :: "r"(_m), "r"(_p) : "memory"); \
    } } while (0)

__device__ __forceinline__ void bulk_g2s(uint32_t dst, const void* src,
                                         uint32_t bytes, uint32_t mbar) {
    asm volatile(
        "cp.async.bulk.shared::cluster.global.mbarrier::complete_tx::bytes [%0], [%1], %2, [%3];"
        :: "r"(dst), "l"(src), "r"(bytes), "r"(mbar) : "memory");
}

__device__ __forceinline__ void ldsm_x4(uint32_t& r0, uint32_t& r1,
                                        uint32_t& r2, uint32_t& r3, uint32_t addr) {
    asm volatile("ldmatrix.sync.aligned.m8n8.x4.shared.b16 {%0,%1,%2,%3}, [%4];"
                 : "=r"(r0), "=r"(r1), "=r"(r2), "=r"(r3) : "r"(addr));
}
__device__ __forceinline__ void ldsm_x4_t(uint32_t& r0, uint32_t& r1,
                                          uint32_t& r2, uint32_t& r3, uint32_t addr) {
    asm volatile("ldmatrix.sync.aligned.m8n8.x4.trans.shared.b16 {%0,%1,%2,%3}, [%4];"
                 : "=r"(r0), "=r"(r1), "=r"(r2), "=r"(r3) : "r"(addr));
}

__device__ __forceinline__ void mma_fp16(float* c, const uint32_t* a,
                                         uint32_t b0, uint32_t b1) {
    asm volatile(
        "mma.sync.aligned.m16n8k16.row.col.f32.f16.f16.f32 "
        "{%0,%1,%2,%3}, {%4,%5,%6,%7}, {%8,%9}, {%0,%1,%2,%3};"
        : "+f"(c[0]), "+f"(c[1]), "+f"(c[2]), "+f"(c[3])
        : "r"(a[0]), "r"(a[1]), "r"(a[2]), "r"(a[3]), "r"(b0), "r"(b1));
}

__device__ __forceinline__ uint32_t pack_bf16(float a, float b) {
    __nv_bfloat162 t = __float22bfloat162_rn(make_float2(a, b));
    return *reinterpret_cast<uint32_t*>(&t);
}
__device__ __forceinline__ uint32_t pack_half(float a, float b) {
    __half2 t = __floats2half2_rn(a, b);
    return *reinterpret_cast<uint32_t*>(&t);
}

// ---------------- asymmetric fp16 GEMM: C = (Ah+Al)[M,K] * B[N,K]^T ---------
// Block 128x256, 8 warps 64x64, K-chunk 64, 3-stage bulk pipeline, 2-MMA.
#define BK       64
#define NCH      (KDIM / BK)
#define A_TB     16384
#define STG_B    (4 * A_TB)              // Ah, Al, B0, B1 = 65536
#define GSTAGES  3
#define GEMM_SMEM (1024 + GSTAGES * STG_B)  // 197632

__device__ __forceinline__ void gemm_body(
    const char* cAh, const char* cAl, const char* cB,
    int mb, int nb, float acc[4][8][4]) {
    extern __shared__ char smem[];
    const uint32_t sb = smem_u32(smem);
    const int tid = threadIdx.x, wid = tid >> 5, lane = tid & 31;
    const int wm = (wid & 1) * 64;
    const int wn = (wid >> 1) * 64;

    const size_t mbB = ((size_t)mb * 16) << 14;
    const size_t nbB0 = ((size_t)(nb * 2) * 16) << 14;
    const size_t nbB1 = ((size_t)(nb * 2 + 1) * 16) << 14;

    if (tid == 0) {
        MBARRIER_INIT(sb, 1); MBARRIER_INIT(sb + 8, 1); MBARRIER_INIT(sb + 16, 1);
    }
    __syncthreads();

    auto issue = [&](int chunk, int buf) {
        const uint32_t st = sb + 1024 + buf * STG_B;
        const uint32_t bar = sb + buf * 8;
        const size_t kB = ((size_t)chunk) << 14;
        MBAR_EXPECT(bar, STG_B);
        bulk_g2s(st,            cAh + mbB + kB,  A_TB, bar);
        bulk_g2s(st + A_TB,     cAl + mbB + kB,  A_TB, bar);
        bulk_g2s(st + 2 * A_TB, cB + nbB0 + kB,  A_TB, bar);
        bulk_g2s(st + 3 * A_TB, cB + nbB1 + kB,  A_TB, bar);
    };

    if (tid == 0) { issue(0, 0); issue(1, 1); issue(2, 2); }

#pragma unroll
    for (int i = 0; i < 4; i++)
#pragma unroll
        for (int j = 0; j < 8; j++)
#pragma unroll
            for (int e = 0; e < 4; e++) acc[i][j][e] = 0.f;

    const int a_row = (lane & 15);
    const uint32_t a_cb = (uint32_t)((lane >> 4) * 16);
    const int b_row = ((lane >> 4) & 1) * 8 + (lane & 7);
    const uint32_t b_cb = (uint32_t)(((lane >> 3) & 1) * 16);

    for (int i = 0; i < NCH; i++) {
        const int stg = i % GSTAGES;
        MBARRIER_WAIT_PARITY(sb + stg * 8, (i / GSTAGES) & 1);

        const uint32_t st = sb + 1024 + stg * STG_B;
        const uint32_t aH = st, aL = st + A_TB;
        const uint32_t bB = st + 2 * A_TB;   // 256 rows contiguous (two 128-row tiles)

#pragma unroll
        for (int ks = 0; ks < 4; ks++) {
            const uint32_t kb = (uint32_t)(ks * 32);
            uint32_t ah[4][4], al[4][4];
#pragma unroll
            for (int mi = 0; mi < 4; mi++) {
                uint32_t off = SWZ128((uint32_t)((wm + mi * 16 + a_row) * 128) + kb + a_cb);
                ldsm_x4(ah[mi][0], ah[mi][1], ah[mi][2], ah[mi][3], aH + off);
                ldsm_x4(al[mi][0], al[mi][1], al[mi][2], al[mi][3], aL + off);
            }
#pragma unroll
            for (int hb = 0; hb < 2; hb++) {
                uint32_t bf[2][4];
#pragma unroll
                for (int g2 = 0; g2 < 2; g2++) {
                    const int ng = hb * 2 + g2;
                    uint32_t off = SWZ128((uint32_t)((wn + ng * 16 + b_row) * 128) + kb + b_cb);
                    ldsm_x4(bf[g2][0], bf[g2][1], bf[g2][2], bf[g2][3], bB + off);
                }
                // pass 1: Ah x B (16 independent MMAs)
#pragma unroll
                for (int g2 = 0; g2 < 2; g2++)
#pragma unroll
                    for (int mi = 0; mi < 4; mi++) {
                        const int nj = 2 * (hb * 2 + g2);
                        mma_fp16(acc[mi][nj],     ah[mi], bf[g2][0], bf[g2][1]);
                        mma_fp16(acc[mi][nj + 1], ah[mi], bf[g2][2], bf[g2][3]);
                    }
                // pass 2: Al x B
#pragma unroll
                for (int g2 = 0; g2 < 2; g2++)
#pragma unroll
                    for (int mi = 0; mi < 4; mi++) {
                        const int nj = 2 * (hb * 2 + g2);
                        mma_fp16(acc[mi][nj],     al[mi], bf[g2][0], bf[g2][1]);
                        mma_fp16(acc[mi][nj + 1], al[mi], bf[g2][2], bf[g2][3]);
                    }
            }
        }
        __syncthreads();
        if (i + GSTAGES < NCH && tid == 0) issue(i + GSTAGES, stg);
    }
}

__device__ __forceinline__ void gemm_store(float acc[4][8][4], float* Cm, int N,
                                           int m0, int n0) {
    const int tid = threadIdx.x, wid = tid >> 5, lane = tid & 31;
    const int wm = (wid & 1) * 64, wn = (wid >> 1) * 64;
    const int cr = lane >> 2;
    const int cc = (lane & 3) * 2;
#pragma unroll
    for (int mi = 0; mi < 4; mi++) {
#pragma unroll
        for (int nj = 0; nj < 8; nj++) {
            const int r = m0 + wm + mi * 16 + cr;
            const int c = n0 + wn + nj * 8 + cc;
            *(float2*)&Cm[(size_t)r * N + c] = make_float2(acc[mi][nj][0], acc[mi][nj][1]);
            *(float2*)&Cm[(size_t)(r + 8) * N + c] = make_float2(acc[mi][nj][2], acc[mi][nj][3]);
        }
    }
}

// Combined Q/K/V projection GEMM: grid.x = 20 (8 Q | 8 K | 4 V), grid.y = 32
__global__ __launch_bounds__(256, 1)
void gemm_qkv(const __half* __restrict__ xh, const __half* __restrict__ xl,
              const __half* __restrict__ wq, const __half* __restrict__ wk,
              const __half* __restrict__ wv,
              float* __restrict__ qraw, float* __restrict__ kraw, float* __restrict__ vout) {
    const int nx = blockIdx.x;
    const __half* B;
    float* Cm;
    int N, nb;
    if (nx < 8)       { B = wq; Cm = qraw; N = 2 * CDIM; nb = nx; }
    else if (nx < 16) { B = wk; Cm = kraw; N = 2 * CDIM; nb = nx - 8; }
    else              { B = wv; Cm = vout; N = CDIM;     nb = nx - 16; }

    float acc[4][8][4];
    gemm_body((const char*)xh, (const char*)xl, (const char*)B, blockIdx.y, nb, acc);
    gemm_store(acc, Cm, N, blockIdx.y * 128, nb * 256);
}

// Output projection GEMM
__global__ __launch_bounds__(256, 1)
void gemm_out(const __half* __restrict__ Ah, const __half* __restrict__ Al,
              const __half* __restrict__ B, float* __restrict__ Cm, int N) {
    float acc[4][8][4];
    gemm_body((const char*)Ah, (const char*)Al, (const char*)B,
              blockIdx.y, blockIdx.x, acc);
    gemm_store(acc, Cm, N, blockIdx.y * 128, blockIdx.x * 256);
}

// ---------------- fp32 -> (hi,lo) fp16 split, GEMM-A tiled layout ----------
__global__ __launch_bounds__(256)
void convert_split_gemm(const float* __restrict__ src, __half* __restrict__ hi,
                        __half* __restrict__ lo) {
    int i2 = blockIdx.x * 256 + threadIdx.x;
    int row = i2 >> 9, col = (i2 & 511) * 2;
    float2 v = *(const float2*)&src[(size_t)row * CDIM + col];
    float h0 = __half2float(__float2half(v.x));
    float h1 = __half2float(__float2half(v.y));
    size_t off = gemmA_off(row, col);
    *(uint32_t*)((char*)hi + off) = pack_half(h0, h1);
    *(uint32_t*)((char*)lo + off) = pack_half(v.x - h0, v.y - h1);
}

// fp32 -> fp16 hi/lo in ATTENTION tiled layout (for V)
__global__ __launch_bounds__(256)
void convert_split_att(const float* __restrict__ src, __half* __restrict__ hi,
                       __half* __restrict__ lo) {
    int i2 = blockIdx.x * 256 + threadIdx.x;
    int bt = i2 >> 9, col = (i2 & 511) * 2;
    int b = bt >> 11, t = bt & (SEQ - 1);
    int h = col >> 6, d = col & 63;
    float2 v = *(const float2*)&src[(size_t)bt * CDIM + col];
    float h0 = __half2float(__float2half(v.x));
    float h1 = __half2float(__float2half(v.y));
    size_t off = att_off(b, h, t, d);
    *(uint32_t*)((char*)hi + off) = pack_half(h0, h1);
    *(uint32_t*)((char*)lo + off) = pack_half(v.x - h0, v.y - h1);
}

// ---------------- weight transpose -> single fp16, GEMM-A tiled layout ------
__global__ __launch_bounds__(256)
void transpose_half(const float* __restrict__ W, __half* __restrict__ Hh,
                    int K, int N) {
    __shared__ float t[32][33];
    const int tx = threadIdx.x, ty = threadIdx.y;
    const int n0 = blockIdx.x * 32, k0 = blockIdx.y * 32;
#pragma unroll
    for (int i = 0; i < 32; i += 8)
        t[ty + i][tx] = W[(size_t)(k0 + ty + i) * N + n0 + tx];
    __syncthreads();
#pragma unroll
    for (int i = 0; i < 32; i += 8) {
        float v = t[tx][ty + i];
        size_t off = gemmA_off(n0 + ty + i, k0 + tx);
        *(__half*)((char*)Hh + off) = __float2half(v);
    }
}

// ---------------- amp/phase transform -> fp16 (Q single, K hi/lo) ----------
__device__ __forceinline__ float softplus_f(float a) {
    return (a > 20.f) ? a : log1pf(expf(a));
}

__global__ __launch_bounds__(256)
void transform_qk_fp16() {
    int i2 = blockIdx.x * 256 + threadIdx.x;
    int c2 = i2 * 2;
    int bt = c2 >> 10;
    int c  = c2 & 1023;
    int b = bt >> 11, t = bt & (SEQ - 1);
    int h = c >> 6, d = c & 63;
    size_t rbase = (size_t)bt * (2 * CDIM);
    size_t off = att_off(b, h, t, d);

    float qa0 = g_qraw[rbase + c],        qa1 = g_qraw[rbase + c + 1];
    float qp0 = g_qraw[rbase + CDIM + c], qp1 = g_qraw[rbase + CDIM + c + 1];
    float ka0 = g_kraw[rbase + c],        ka1 = g_kraw[rbase + c + 1];
    float kp0 = g_kraw[rbase + CDIM + c], kp1 = g_kraw[rbase + CDIM + c + 1];

    float qs0 = softplus_f(qa0), qs1 = softplus_f(qa1);
    float ks0 = softplus_f(ka0), ks1 = softplus_f(ka1);
    float s0, c0, s1, c1, s2, c2f, s3, c3;
    sincosf(qp0, &s0, &c0); sincosf(qp1, &s1, &c1);
    sincosf(kp0, &s2, &c2f); sincosf(kp1, &s3, &c3);

    *(uint32_t*)((char*)g_qr + off) = pack_half(qs0 * c0, qs1 * c1);
    *(uint32_t*)((char*)g_qi + off) = pack_half(qs0 * s0, qs1 * s1);

    float kr0 = ks0 * c2f, kr1 = ks1 * c3;
    float ki0 = ks0 * s2,  ki1 = ks1 * s3;
    float krh0 = __half2float(__float2half(kr0)), krh1 = __half2float(__float2half(kr1));
    float kih0 = __half2float(__float2half(ki0)), kih1 = __half2float(__float2half(ki1));
    *(uint32_t*)((char*)g_krh + off) = pack_half(krh0, krh1);
    *(uint32_t*)((char*)g_krl + off) = pack_half(kr0 - krh0, kr1 - krh1);
    *(uint32_t*)((char*)g_kih + off) = pack_half(kih0, kih1);
    *(uint32_t*)((char*)g_kil + off) = pack_half(ki0 - kih0, ki1 - kih1);
}

__global__ void gate_init(const float* __restrict__ theta) {
    int i = blockIdx.x * 256 + threadIdx.x;
    int h = i >> 11, s = i & (SEQ - 1);
    float th = theta[h] * (1.0f / GAMMA_F);
    float sn, cs;
    sincosf(th * (float)s, &sn, &cs);
    g_gate[i] = make_float2(cs, sn);
}

// ---------------- fp16 tensor-core flash attention with moiré gate ----------
#define AQT 128
#define AST 64
#define AQ_TILE 16384
#define AKV_TILE 8192
#define AKV_BUF (6 * AKV_TILE)              // 49152
#define AKV_STAGES 3
#define ATT_SMEM (1024 + 2 * AQ_TILE + AKV_STAGES * AKV_BUF)  // 181248

__global__ __launch_bounds__(256)
void attn_mma() {
    extern __shared__ char smem[];
    const uint32_t sb = smem_u32(smem);
    const uint32_t sQ  = sb + 1024;
    const uint32_t sKV = sQ + 2 * AQ_TILE;

    const int tid = threadIdx.x, w = tid >> 5, lane = tid & 31;
    const int q0 = (int)(gridDim.x - 1 - blockIdx.x) * AQT;
    const int h = blockIdx.y, b = blockIdx.z;
    const int nS = q0 / AST + 2;

    const size_t bhB = ((size_t)((b * HEADS + h) * 32)) << 13;

    if (tid == 0) {
        MBARRIER_INIT(sb, 1);
        MBARRIER_INIT(sb + 8, 1);
        MBARRIER_INIT(sb + 16, 1);
        MBARRIER_INIT(sb + 24, 1);
    }
    __syncthreads();

    auto issue_kv = [&](int chunk, int buf) {
        const uint32_t st = sKV + buf * AKV_BUF;
        const uint32_t bar = sb + 8 + buf * 8;
        const size_t src = bhB + (((size_t)chunk) << 13);
        MBAR_EXPECT(bar, AKV_BUF);
        bulk_g2s(st,                (const char*)g_krh + src, AKV_TILE, bar);
        bulk_g2s(st + AKV_TILE,     (const char*)g_krl + src, AKV_TILE, bar);
        bulk_g2s(st + 2 * AKV_TILE, (const char*)g_kih + src, AKV_TILE, bar);
        bulk_g2s(st + 3 * AKV_TILE, (const char*)g_kil + src, AKV_TILE, bar);
        bulk_g2s(st + 4 * AKV_TILE, (const char*)g_vh  + src, AKV_TILE, bar);
        bulk_g2s(st + 5 * AKV_TILE, (const char*)g_vl  + src, AKV_TILE, bar);
    };

    if (tid == 0) {
        const size_t qsrc = bhB + (((size_t)(q0 >> 6)) << 13);
        MBAR_EXPECT(sb, 2 * AQ_TILE);
        bulk_g2s(sQ,           (const char*)g_qr + qsrc, AQ_TILE, sb);
        bulk_g2s(sQ + AQ_TILE, (const char*)g_qi + qsrc, AQ_TILE, sb);
#pragma unroll
        for (int c = 0; c < AKV_STAGES; c++)
            if (c < nS) issue_kv(c, c);
    }

    const int a_row = lane & 15;
    const uint32_t a_cb = (uint32_t)((lane >> 4) * 16);
    const int b_row = ((lane >> 4) & 1) * 8 + (lane & 7);
    const uint32_t b_cb = (uint32_t)(((lane >> 3) & 1) * 16);

    const int t0g = q0 + w * 16 + (lane >> 2);
    const int t1g = t0g + 8;
    const float2 gt0 = g_gate[h * SEQ + t0g];
    const float2 gt1 = g_gate[h * SEQ + t1g];

    float m0 = -INFINITY, m1 = -INFINITY, l0 = 0.f, l1 = 0.f;
    float oacc[8][4];
#pragma unroll
    for (int f = 0; f < 8; f++)
#pragma unroll
        for (int e = 0; e < 4; e++) oacc[f][e] = 0.f;

    MBARRIER_WAIT_PARITY(sb, 0);

    for (int i = 0; i < nS; i++) {
        const int stg = i % AKV_STAGES;
        MBARRIER_WAIT_PARITY(sb + 8 + stg * 8, (i / AKV_STAGES) & 1);

        const int s0 = i * AST;
        const uint32_t kb0 = sKV + stg * AKV_BUF;
        const uint32_t kRH = kb0, kRL = kb0 + AKV_TILE;
        const uint32_t kIH = kb0 + 2 * AKV_TILE, kIL = kb0 + 3 * AKV_TILE;
        const uint32_t vH = kb0 + 4 * AKV_TILE, vL = kb0 + 5 * AKV_TILE;

        float sacc[8][4];
#pragma unroll
        for (int f = 0; f < 8; f++)
#pragma unroll
            for (int e = 0; e < 4; e++) sacc[f][e] = 0.f;

#pragma unroll
        for (int jd = 0; jd < 4; jd++) {
            const uint32_t kb = (uint32_t)(jd * 32);
            const uint32_t offA = SWZ128((uint32_t)((w * 16 + a_row) * 128) + kb + a_cb);
            uint32_t aqr[4], aqi[4];
            ldsm_x4(aqr[0], aqr[1], aqr[2], aqr[3], sQ + offA);
            ldsm_x4(aqi[0], aqi[1], aqi[2], aqi[3], sQ + AQ_TILE + offA);
#pragma unroll
            for (int gp = 0; gp < 2; gp++) {
                uint32_t rh[2][4], rl[2][4], ih[2][4], il[2][4];
#pragma unroll
                for (int g2 = 0; g2 < 2; g2++) {
                    const int g = gp * 2 + g2;
                    const uint32_t offB = SWZ128((uint32_t)((g * 16 + b_row) * 128) + kb + b_cb);
                    ldsm_x4(rh[g2][0], rh[g2][1], rh[g2][2], rh[g2][3], kRH + offB);
                    ldsm_x4(rl[g2][0], rl[g2][1], rl[g2][2], rl[g2][3], kRL + offB);
                    ldsm_x4(ih[g2][0], ih[g2][1], ih[g2][2], ih[g2][3], kIH + offB);
                    ldsm_x4(il[g2][0], il[g2][1], il[g2][2], il[g2][3], kIL + offB);
                }
#pragma unroll
                for (int g2 = 0; g2 < 2; g2++) {
                    const int s2 = 2 * (gp * 2 + g2);
                    mma_fp16(sacc[s2],     aqr, rh[g2][0], rh[g2][1]);
                    mma_fp16(sacc[s2 + 1], aqr, rh[g2][2], rh[g2][3]);
                }
#pragma unroll
                for (int g2 = 0; g2 < 2; g2++) {
                    const int s2 = 2 * (gp * 2 + g2);
                    mma_fp16(sacc[s2],     aqi, ih[g2][0], ih[g2][1]);
                    mma_fp16(sacc[s2 + 1], aqi, ih[g2][2], ih[g2][3]);
                }
#pragma unroll
                for (int g2 = 0; g2 < 2; g2++) {
                    const int s2 = 2 * (gp * 2 + g2);
                    mma_fp16(sacc[s2],     aqr, rl[g2][0], rl[g2][1]);
                    mma_fp16(sacc[s2 + 1], aqr, rl[g2][2], rl[g2][3]);
                }
#pragma unroll
                for (int g2 = 0; g2 < 2; g2++) {
                    const int s2 = 2 * (gp * 2 + g2);
                    mma_fp16(sacc[s2],     aqi, il[g2][0], il[g2][1]);
                    mma_fp16(sacc[s2 + 1], aqi, il[g2][2], il[g2][3]);
                }
            }
        }

        float pm0 = -INFINITY, pm1 = -INFINITY;
#pragma unroll
        for (int f = 0; f < 8; f++) {
            const int sb2 = s0 + f * 8 + (lane & 3) * 2;
            const float2 gs0 = g_gate[h * SEQ + sb2];
            const float2 gs1 = g_gate[h * SEQ + sb2 + 1];
            float v00 = sacc[f][0] * SCALE_F * (gs0.x * gt0.x + gs0.y * gt0.y);
            float v01 = sacc[f][1] * SCALE_F * (gs1.x * gt0.x + gs1.y * gt0.y);
            float v10 = sacc[f][2] * SCALE_F * (gs0.x * gt1.x + gs0.y * gt1.y);
            float v11 = sacc[f][3] * SCALE_F * (gs1.x * gt1.x + gs1.y * gt1.y);
            if (sb2 > t0g)     v00 = -INFINITY;
            if (sb2 + 1 > t0g) v01 = -INFINITY;
            if (sb2 > t1g)     v10 = -INFINITY;
            if (sb2 + 1 > t1g) v11 = -INFINITY;
            sacc[f][0] = v00; sacc[f][1] = v01; sacc[f][2] = v10; sacc[f][3] = v11;
            pm0 = fmaxf(pm0, fmaxf(v00, v01));
            pm1 = fmaxf(pm1, fmaxf(v10, v11));
        }
        pm0 = fmaxf(pm0, __shfl_xor_sync(0xffffffffu, pm0, 1));
        pm0 = fmaxf(pm0, __shfl_xor_sync(0xffffffffu, pm0, 2));
        pm1 = fmaxf(pm1, __shfl_xor_sync(0xffffffffu, pm1, 1));
        pm1 = fmaxf(pm1, __shfl_xor_sync(0xffffffffu, pm1, 2));

        const float mn0 = fmaxf(m0, pm0), mn1 = fmaxf(m1, pm1);
        const float cr0 = __expf(m0 - mn0), cr1 = __expf(m1 - mn1);
        float rs0 = 0.f, rs1 = 0.f;
#pragma unroll
        for (int f = 0; f < 8; f++) {
            sacc[f][0] = __expf(sacc[f][0] - mn0);
            sacc[f][1] = __expf(sacc[f][1] - mn0);
            sacc[f][2] = __expf(sacc[f][2] - mn1);
            sacc[f][3] = __expf(sacc[f][3] - mn1);
            rs0 += sacc[f][0] + sacc[f][1];
            rs1 += sacc[f][2] + sacc[f][3];
        }
        rs0 += __shfl_xor_sync(0xffffffffu, rs0, 1);
        rs0 += __shfl_xor_sync(0xffffffffu, rs0, 2);
        rs1 += __shfl_xor_sync(0xffffffffu, rs1, 1);
        rs1 += __shfl_xor_sync(0xffffffffu, rs1, 2);
        l0 = l0 * cr0 + rs0; m0 = mn0;
        l1 = l1 * cr1 + rs1; m1 = mn1;
#pragma unroll
        for (int f = 0; f < 8; f++) {
            oacc[f][0] *= cr0; oacc[f][1] *= cr0;
            oacc[f][2] *= cr1; oacc[f][3] *= cr1;
        }

#pragma unroll
        for (int j = 0; j < 4; j++) {
            uint32_t ph[4] = {
                pack_half(sacc[2 * j][0],     sacc[2 * j][1]),
                pack_half(sacc[2 * j][2],     sacc[2 * j][3]),
                pack_half(sacc[2 * j + 1][0], sacc[2 * j + 1][1]),
                pack_half(sacc[2 * j + 1][2], sacc[2 * j + 1][3])};
#pragma unroll
            for (int dgp = 0; dgp < 2; dgp++) {
                uint32_t vh[2][4], vl[2][4];
#pragma unroll
                for (int d2 = 0; d2 < 2; d2++) {
                    const int dg = dgp * 2 + d2;
                    const uint32_t offV = SWZ128((uint32_t)((16 * j + a_row) * 128) +
                                                 (uint32_t)(dg * 32) + a_cb);
                    ldsm_x4_t(vh[d2][0], vh[d2][1], vh[d2][2], vh[d2][3], vH + offV);
                    ldsm_x4_t(vl[d2][0], vl[d2][1], vl[d2][2], vl[d2][3], vL + offV);
                }
#pragma unroll
                for (int d2 = 0; d2 < 2; d2++) {
                    const int o2 = 2 * (dgp * 2 + d2);
                    mma_fp16(oacc[o2],     ph, vh[d2][0], vh[d2][1]);
                    mma_fp16(oacc[o2 + 1], ph, vh[d2][2], vh[d2][3]);
                }
#pragma unroll
                for (int d2 = 0; d2 < 2; d2++) {
                    const int o2 = 2 * (dgp * 2 + d2);
                    mma_fp16(oacc[o2],     ph, vl[d2][0], vl[d2][1]);
                    mma_fp16(oacc[o2 + 1], ph, vl[d2][2], vl[d2][3]);
                }
            }
        }
        __syncthreads();
        if (i + AKV_STAGES < nS && tid == 0) issue_kv(i + AKV_STAGES, stg);
    }

    // epilogue: normalize, write fp16 hi/lo in GEMM-A tiled layout
    const float iv0 = 1.0f / l0, iv1 = 1.0f / l1;
#pragma unroll
    for (int f = 0; f < 8; f++) {
        const int d = f * 8 + (lane & 3) * 2;
        float o00 = oacc[f][0] * iv0, o01 = oacc[f][1] * iv0;
        float o10 = oacc[f][2] * iv1, o11 = oacc[f][3] * iv1;
        float h00 = __half2float(__float2half(o00));
        float h01 = __half2float(__float2half(o01));
        float h10 = __half2float(__float2half(o10));
        float h11 = __half2float(__float2half(o11));
        size_t off0 = gemmA_off(b * SEQ + t0g, h * 64 + d);
        size_t off1 = gemmA_off(b * SEQ + t1g, h * 64 + d);
        *(uint32_t*)((char*)g_ah + off0) = pack_half(h00, h01);
        *(uint32_t*)((char*)g_al + off0) = pack_half(o00 - h00, o01 - h01);
        *(uint32_t*)((char*)g_ah + off1) = pack_half(h10, h11);
        *(uint32_t*)((char*)g_al + off1) = pack_half(o10 - h10, o11 - h11);
    }
}

// ---------------- launch ---------------------------------------------------
extern "C" void kernel_launch(void* const* d_in, const int* in_sizes, int n_in,
                              void* d_out, int out_size) {
    const float* x     = (const float*)d_in[0];
    const float* Wq    = (const float*)d_in[1];
    const float* Wk    = (const float*)d_in[2];
    const float* Wv    = (const float*)d_in[3];
    const float* Wo    = (const float*)d_in[4];
    const float* theta = (const float*)d_in[5];
    float* out = (float*)d_out;

    float *qraw, *kraw, *v;
    __half *xh, *xl, *ah, *al, *vh, *vl, *wq, *wk, *wv, *wo;
    cudaGetSymbolAddress((void**)&qraw, g_qraw);
    cudaGetSymbolAddress((void**)&kraw, g_kraw);
    cudaGetSymbolAddress((void**)&v,    g_v);
    cudaGetSymbolAddress((void**)&xh,  g_xh);
    cudaGetSymbolAddress((void**)&xl,  g_xl);
    cudaGetSymbolAddress((void**)&ah,  g_ah);
    cudaGetSymbolAddress((void**)&al,  g_al);
    cudaGetSymbolAddress((void**)&vh,  g_vh);
    cudaGetSymbolAddress((void**)&vl,  g_vl);
    cudaGetSymbolAddress((void**)&wq,  g_wq);
    cudaGetSymbolAddress((void**)&wk,  g_wk);
    cudaGetSymbolAddress((void**)&wv,  g_wv);
    cudaGetSymbolAddress((void**)&wo,  g_wo);

    cudaFuncSetAttribute(gemm_qkv,
                         cudaFuncAttributeMaxDynamicSharedMemorySize, GEMM_SMEM);
    cudaFuncSetAttribute(gemm_out,
                         cudaFuncAttributeMaxDynamicSharedMemorySize, GEMM_SMEM);
    cudaFuncSetAttribute(attn_mma,
                         cudaFuncAttributeMaxDynamicSharedMemorySize, ATT_SMEM);

    dim3 tblk(32, 8);

    convert_split_gemm<<<MROWS * CDIM / 2 / 256, 256>>>(x, xh, xl);
    gate_init<<<HEADS * SEQ / 256, 256>>>(theta);
    transpose_half<<<dim3(2 * CDIM / 32, CDIM / 32), tblk>>>(Wq, wq, CDIM, 2 * CDIM);
    transpose_half<<<dim3(2 * CDIM / 32, CDIM / 32), tblk>>>(Wk, wk, CDIM, 2 * CDIM);
    transpose_half<<<dim3(CDIM / 32, CDIM / 32), tblk>>>(Wv, wv, CDIM, CDIM);
    transpose_half<<<dim3(CDIM / 32, CDIM / 32), tblk>>>(Wo, wo, CDIM, CDIM);

    gemm_qkv<<<dim3(20, MROWS / 128), 256, GEMM_SMEM>>>(
        xh, xl, wq, wk, wv, qraw, kraw, v);

    transform_qk_fp16<<<MROWS * CDIM / 2 / 256, 256>>>();
    convert_split_att<<<MROWS * CDIM / 2 / 256, 256>>>(v, vh, vl);

    attn_mma<<<dim3(SEQ / AQT, HEADS, BATCH), 256, ATT_SMEM>>>();

    gemm_out<<<dim3(CDIM / 256, MROWS / 128), 256, GEMM_SMEM>>>(ah, al, wo, out, CDIM);
}

// round 12
// speedup vs baseline: 1.7175x; 1.1374x over previous
#include <cuda_runtime.h>
#include <cuda_bf16.h>
#include <cuda_fp16.h>
#include <cstdint>
#include <math.h>

// Problem constants
#define BATCH   2
#define SEQ     2048
#define CDIM    1024
#define HEADS   16
#define HDIM    64
#define GAMMA_F 8.0f
#define SCALE_F 0.125f
#define MROWS   (BATCH*SEQ)          // 4096
#define KDIM    1024

// ---------------- scratch (device globals; no allocation allowed) ----------
__device__ float g_qraw[MROWS * 2 * CDIM];
__device__ float g_kraw[MROWS * 2 * CDIM];
__device__ float g_v   [MROWS * CDIM];

// fp16 GEMM operands (pre-swizzled tile-blocked layouts)
__device__ __half g_xh [MROWS * CDIM];
__device__ __half g_xl [MROWS * CDIM];
__device__ __half g_ah [MROWS * CDIM];
__device__ __half g_al [MROWS * CDIM];
__device__ __half g_wq [2 * CDIM * CDIM];
__device__ __half g_wk [2 * CDIM * CDIM];
__device__ __half g_wv [CDIM * CDIM];
__device__ __half g_wo [CDIM * CDIM];

// attention operands: ALL single fp16
__device__ __half g_qr [MROWS * CDIM];
__device__ __half g_qi [MROWS * CDIM];
__device__ __half g_kr [MROWS * CDIM];
__device__ __half g_ki [MROWS * CDIM];
__device__ __half g_vv [MROWS * CDIM];
__device__ float2 g_gate[HEADS * SEQ];

// ---------------- helpers ---------------------------------------------------
__device__ __forceinline__ uint32_t smem_u32(const void* p) {
    uint32_t a;
    asm("{ .reg .u64 t; cvta.to.shared.u64 t, %1; cvt.u32.u64 %0, t; }"
        : "=r"(a) : "l"(p));
    return a;
}
#define SWZ128(o) ((o) ^ (((o) >> 3) & 0x70))

__device__ __forceinline__ size_t gemmA_off(int row, int col) {
    return ((size_t)((row >> 7) * 16 + (col >> 6)) << 14) +
           SWZ128((uint32_t)((row & 127) * 128 + (col & 63) * 2));
}
__device__ __forceinline__ size_t att_off(int b, int h, int t, int d) {
    return ((size_t)((b * HEADS + h) * 32 + (t >> 6)) << 13) +
           SWZ128((uint32_t)((t & 63) * 128 + d * 2));
}

#define MBARRIER_INIT(mbar, count) \
    asm volatile("mbarrier.init.shared.b64 [%0], %1;" :: "r"((uint32_t)(mbar)), "r"((uint32_t)(count)) : "memory")
#define MBAR_EXPECT(mbar, bytes) \
    asm volatile("mbarrier.arrive.expect_tx.shared.b64 _, [%0], %1;" :: "r"((uint32_t)(mbar)), "r"((uint32_t)(bytes)) : "memory")

#define MBARRIER_WAIT_PARITY(mbar, parity) do { \
    uint32_t _m = (uint32_t)(mbar); uint32_t _p = (uint32_t)(parity); uint32_t _d; \
    asm volatile("{\n\t.reg .pred p;\n\t" \
        "mbarrier.try_wait.parity.acquire.cta.shared::cta.b64 p, [%1], %2;\n\t" \
        "selp.b32 %0, 1, 0, p;\n\t}" : "=r"(_d) : "r"(_m), "r"(_p) : "memory"); \
    if (!_d) { \
        asm volatile("{\n\t.reg .pred P1;\n\t" \
            "WL_%=:\n\t" \
            "mbarrier.try_wait.parity.acquire.cta.shared::cta.b64 P1, [%0], %1, 0x989680;\n\t" \
            "@P1 bra.uni WD_%=;\n\tbra.uni WL_%=;\n\tWD_%=:\n\t}" \
            :: "r"(_m), "r"(_p) : "memory"); \
    } } while (0)

__device__ __forceinline__ void bulk_g2s(uint32_t dst, const void* src,
                                         uint32_t bytes, uint32_t mbar) {
    asm volatile(
        "cp.async.bulk.shared::cluster.global.mbarrier::complete_tx::bytes [%0], [%1], %2, [%3];"
        :: "r"(dst), "l"(src), "r"(bytes), "r"(mbar) : "memory");
}

__device__ __forceinline__ void ldsm_x4(uint32_t& r0, uint32_t& r1,
                                        uint32_t& r2, uint32_t& r3, uint32_t addr) {
    asm volatile("ldmatrix.sync.aligned.m8n8.x4.shared.b16 {%0,%1,%2,%3}, [%4];"
                 : "=r"(r0), "=r"(r1), "=r"(r2), "=r"(r3) : "r"(addr));
}
__device__ __forceinline__ void ldsm_x4_t(uint32_t& r0, uint32_t& r1,
                                          uint32_t& r2, uint32_t& r3, uint32_t addr) {
    asm volatile("ldmatrix.sync.aligned.m8n8.x4.trans.shared.b16 {%0,%1,%2,%3}, [%4];"
                 : "=r"(r0), "=r"(r1), "=r"(r2), "=r"(r3) : "r"(addr));
}

__device__ __forceinline__ void mma_fp16(float* c, const uint32_t* a,
                                         uint32_t b0, uint32_t b1) {
    asm volatile(
        "mma.sync.aligned.m16n8k16.row.col.f32.f16.f16.f32 "
        "{%0,%1,%2,%3}, {%4,%5,%6,%7}, {%8,%9}, {%0,%1,%2,%3};"
        : "+f"(c[0]), "+f"(c[1]), "+f"(c[2]), "+f"(c[3])
        : "r"(a[0]), "r"(a[1]), "r"(a[2]), "r"(a[3]), "r"(b0), "r"(b1));
}

__device__ __forceinline__ uint32_t pack_half(float a, float b) {
    __half2 t = __floats2half2_rn(a, b);
    return *reinterpret_cast<uint32_t*>(&t);
}

// ---------------- asymmetric fp16 GEMM (unchanged from R11, validated) ------
#define BK       64
#define NCH      (KDIM / BK)
#define A_TB     16384
#define STG_B    (4 * A_TB)              // 65536
#define GSTAGES  3
#define GEMM_SMEM (1024 + GSTAGES * STG_B)  // 197632

__device__ __forceinline__ void gemm_body(
    const char* cAh, const char* cAl, const char* cB,
    int mb, int nb, float acc[4][8][4]) {
    extern __shared__ char smem[];
    const uint32_t sb = smem_u32(smem);
    const int tid = threadIdx.x, wid = tid >> 5, lane = tid & 31;
    const int wm = (wid & 1) * 64;
    const int wn = (wid >> 1) * 64;

    const size_t mbB = ((size_t)mb * 16) << 14;
    const size_t nbB0 = ((size_t)(nb * 2) * 16) << 14;
    const size_t nbB1 = ((size_t)(nb * 2 + 1) * 16) << 14;

    if (tid == 0) {
        MBARRIER_INIT(sb, 1); MBARRIER_INIT(sb + 8, 1); MBARRIER_INIT(sb + 16, 1);
    }
    __syncthreads();

    auto issue = [&](int chunk, int buf) {
        const uint32_t st = sb + 1024 + buf * STG_B;
        const uint32_t bar = sb + buf * 8;
        const size_t kB = ((size_t)chunk) << 14;
        MBAR_EXPECT(bar, STG_B);
        bulk_g2s(st,            cAh + mbB + kB,  A_TB, bar);
        bulk_g2s(st + A_TB,     cAl + mbB + kB,  A_TB, bar);
        bulk_g2s(st + 2 * A_TB, cB + nbB0 + kB,  A_TB, bar);
        bulk_g2s(st + 3 * A_TB, cB + nbB1 + kB,  A_TB, bar);
    };

    if (tid == 0) { issue(0, 0); issue(1, 1); issue(2, 2); }

#pragma unroll
    for (int i = 0; i < 4; i++)
#pragma unroll
        for (int j = 0; j < 8; j++)
#pragma unroll
            for (int e = 0; e < 4; e++) acc[i][j][e] = 0.f;

    const int a_row = (lane & 15);
    const uint32_t a_cb = (uint32_t)((lane >> 4) * 16);
    const int b_row = ((lane >> 4) & 1) * 8 + (lane & 7);
    const uint32_t b_cb = (uint32_t)(((lane >> 3) & 1) * 16);

    for (int i = 0; i < NCH; i++) {
        const int stg = i % GSTAGES;
        MBARRIER_WAIT_PARITY(sb + stg * 8, (i / GSTAGES) & 1);

        const uint32_t st = sb + 1024 + stg * STG_B;
        const uint32_t aH = st, aL = st + A_TB;
        const uint32_t bB = st + 2 * A_TB;

#pragma unroll
        for (int ks = 0; ks < 4; ks++) {
            const uint32_t kb = (uint32_t)(ks * 32);
            uint32_t ah[4][4], al[4][4];
#pragma unroll
            for (int mi = 0; mi < 4; mi++) {
                uint32_t off = SWZ128((uint32_t)((wm + mi * 16 + a_row) * 128) + kb + a_cb);
                ldsm_x4(ah[mi][0], ah[mi][1], ah[mi][2], ah[mi][3], aH + off);
                ldsm_x4(al[mi][0], al[mi][1], al[mi][2], al[mi][3], aL + off);
            }
#pragma unroll
            for (int hb = 0; hb < 2; hb++) {
                uint32_t bf[2][4];
#pragma unroll
                for (int g2 = 0; g2 < 2; g2++) {
                    const int ng = hb * 2 + g2;
                    uint32_t off = SWZ128((uint32_t)((wn + ng * 16 + b_row) * 128) + kb + b_cb);
                    ldsm_x4(bf[g2][0], bf[g2][1], bf[g2][2], bf[g2][3], bB + off);
                }
#pragma unroll
                for (int g2 = 0; g2 < 2; g2++)
#pragma unroll
                    for (int mi = 0; mi < 4; mi++) {
                        const int nj = 2 * (hb * 2 + g2);
                        mma_fp16(acc[mi][nj],     ah[mi], bf[g2][0], bf[g2][1]);
                        mma_fp16(acc[mi][nj + 1], ah[mi], bf[g2][2], bf[g2][3]);
                    }
#pragma unroll
                for (int g2 = 0; g2 < 2; g2++)
#pragma unroll
                    for (int mi = 0; mi < 4; mi++) {
                        const int nj = 2 * (hb * 2 + g2);
                        mma_fp16(acc[mi][nj],     al[mi], bf[g2][0], bf[g2][1]);
                        mma_fp16(acc[mi][nj + 1], al[mi], bf[g2][2], bf[g2][3]);
                    }
            }
        }
        __syncthreads();
        if (i + GSTAGES < NCH && tid == 0) issue(i + GSTAGES, stg);
    }
}

__device__ __forceinline__ void gemm_store(float acc[4][8][4], float* Cm, int N,
                                           int m0, int n0) {
    const int tid = threadIdx.x, wid = tid >> 5, lane = tid & 31;
    const int wm = (wid & 1) * 64, wn = (wid >> 1) * 64;
    const int cr = lane >> 2;
    const int cc = (lane & 3) * 2;
#pragma unroll
    for (int mi = 0; mi < 4; mi++) {
#pragma unroll
        for (int nj = 0; nj < 8; nj++) {
            const int r = m0 + wm + mi * 16 + cr;
            const int c = n0 + wn + nj * 8 + cc;
            *(float2*)&Cm[(size_t)r * N + c] = make_float2(acc[mi][nj][0], acc[mi][nj][1]);
            *(float2*)&Cm[(size_t)(r + 8) * N + c] = make_float2(acc[mi][nj][2], acc[mi][nj][3]);
        }
    }
}

// Combined Q/K/V projection GEMM: grid.x = 20 (8 Q | 8 K | 4 V), grid.y = 32
__global__ __launch_bounds__(256, 1)
void gemm_qkv(const __half* __restrict__ xh, const __half* __restrict__ xl,
              const __half* __restrict__ wq, const __half* __restrict__ wk,
              const __half* __restrict__ wv,
              float* __restrict__ qraw, float* __restrict__ kraw, float* __restrict__ vout) {
    const int nx = blockIdx.x;
    const __half* B;
    float* Cm;
    int N, nb;
    if (nx < 8)       { B = wq; Cm = qraw; N = 2 * CDIM; nb = nx; }
    else if (nx < 16) { B = wk; Cm = kraw; N = 2 * CDIM; nb = nx - 8; }
    else              { B = wv; Cm = vout; N = CDIM;     nb = nx - 16; }

    float acc[4][8][4];
    gemm_body((const char*)xh, (const char*)xl, (const char*)B, blockIdx.y, nb, acc);
    gemm_store(acc, Cm, N, blockIdx.y * 128, nb * 256);
}

// Output projection GEMM
__global__ __launch_bounds__(256, 1)
void gemm_out(const __half* __restrict__ Ah, const __half* __restrict__ Al,
              const __half* __restrict__ B, float* __restrict__ Cm, int N) {
    float acc[4][8][4];
    gemm_body((const char*)Ah, (const char*)Al, (const char*)B,
              blockIdx.y, blockIdx.x, acc);
    gemm_store(acc, Cm, N, blockIdx.y * 128, blockIdx.x * 256);
}

// ---------------- fp32 -> (hi,lo) fp16 split, GEMM-A tiled layout ----------
__global__ __launch_bounds__(256)
void convert_split_gemm(const float* __restrict__ src, __half* __restrict__ hi,
                        __half* __restrict__ lo) {
    int i2 = blockIdx.x * 256 + threadIdx.x;
    int row = i2 >> 9, col = (i2 & 511) * 2;
    float2 v = *(const float2*)&src[(size_t)row * CDIM + col];
    float h0 = __half2float(__float2half(v.x));
    float h1 = __half2float(__float2half(v.y));
    size_t off = gemmA_off(row, col);
    *(uint32_t*)((char*)hi + off) = pack_half(h0, h1);
    *(uint32_t*)((char*)lo + off) = pack_half(v.x - h0, v.y - h1);
}

// fp32 -> single fp16 in ATTENTION tiled layout (for V)
__global__ __launch_bounds__(256)
void convert_att_single(const float* __restrict__ src, __half* __restrict__ dst) {
    int i2 = blockIdx.x * 256 + threadIdx.x;
    int bt = i2 >> 9, col = (i2 & 511) * 2;
    int b = bt >> 11, t = bt & (SEQ - 1);
    int h = col >> 6, d = col & 63;
    float2 v = *(const float2*)&src[(size_t)bt * CDIM + col];
    size_t off = att_off(b, h, t, d);
    *(uint32_t*)((char*)dst + off) = pack_half(v.x, v.y);
}

// ---------------- weight transpose -> single fp16, GEMM-A tiled layout ------
__global__ __launch_bounds__(256)
void transpose_half(const float* __restrict__ W, __half* __restrict__ Hh,
                    int K, int N) {
    __shared__ float t[32][33];
    const int tx = threadIdx.x, ty = threadIdx.y;
    const int n0 = blockIdx.x * 32, k0 = blockIdx.y * 32;
#pragma unroll
    for (int i = 0; i < 32; i += 8)
        t[ty + i][tx] = W[(size_t)(k0 + ty + i) * N + n0 + tx];
    __syncthreads();
#pragma unroll
    for (int i = 0; i < 32; i += 8) {
        float v = t[tx][ty + i];
        size_t off = gemmA_off(n0 + ty + i, k0 + tx);
        *(__half*)((char*)Hh + off) = __float2half(v);
    }
}

// ---------------- amp/phase transform -> single fp16 ------------------------
__device__ __forceinline__ float softplus_f(float a) {
    return (a > 20.f) ? a : log1pf(expf(a));
}

__global__ __launch_bounds__(256)
void transform_qk_fp16() {
    int i2 = blockIdx.x * 256 + threadIdx.x;
    int c2 = i2 * 2;
    int bt = c2 >> 10;
    int c  = c2 & 1023;
    int b = bt >> 11, t = bt & (SEQ - 1);
    int h = c >> 6, d = c & 63;
    size_t rbase = (size_t)bt * (2 * CDIM);
    size_t off = att_off(b, h, t, d);

    float qa0 = g_qraw[rbase + c],        qa1 = g_qraw[rbase + c + 1];
    float qp0 = g_qraw[rbase + CDIM + c], qp1 = g_qraw[rbase + CDIM + c + 1];
    float ka0 = g_kraw[rbase + c],        ka1 = g_kraw[rbase + c + 1];
    float kp0 = g_kraw[rbase + CDIM + c], kp1 = g_kraw[rbase + CDIM + c + 1];

    float qs0 = softplus_f(qa0), qs1 = softplus_f(qa1);
    float ks0 = softplus_f(ka0), ks1 = softplus_f(ka1);
    float s0, c0, s1, c1, s2, c2f, s3, c3;
    sincosf(qp0, &s0, &c0); sincosf(qp1, &s1, &c1);
    sincosf(kp0, &s2, &c2f); sincosf(kp1, &s3, &c3);

    *(uint32_t*)((char*)g_qr + off) = pack_half(qs0 * c0, qs1 * c1);
    *(uint32_t*)((char*)g_qi + off) = pack_half(qs0 * s0, qs1 * s1);
    *(uint32_t*)((char*)g_kr + off) = pack_half(ks0 * c2f, ks1 * c3);
    *(uint32_t*)((char*)g_ki + off) = pack_half(ks0 * s2, ks1 * s3);
}

__global__ void gate_init(const float* __restrict__ theta) {
    int i = blockIdx.x * 256 + threadIdx.x;
    int h = i >> 11, s = i & (SEQ - 1);
    float th = theta[h] * (1.0f / GAMMA_F);
    float sn, cs;
    sincosf(th * (float)s, &sn, &cs);
    g_gate[i] = make_float2(cs, sn);
}

// ---------------- fully fp16 flash attention with moiré gate ----------------
// Q,K,V,P all single fp16: 2 S-passes + 1 PV-pass. 4-stage KV pipeline.
#define AQT 128
#define AST 64
#define AQ_TILE 16384
#define AKV_TILE 8192
#define AKV_BUF (3 * AKV_TILE)              // kr, ki, v = 24576
#define AKV_STAGES 4
#define ATT_SMEM (1024 + 2 * AQ_TILE + AKV_STAGES * AKV_BUF)  // 132096

__global__ __launch_bounds__(256)
void attn_mma() {
    extern __shared__ char smem[];
    const uint32_t sb = smem_u32(smem);
    const uint32_t sQ  = sb + 1024;
    const uint32_t sKV = sQ + 2 * AQ_TILE;

    const int tid = threadIdx.x, w = tid >> 5, lane = tid & 31;
    const int q0 = (int)(gridDim.x - 1 - blockIdx.x) * AQT;
    const int h = blockIdx.y, b = blockIdx.z;
    const int nS = q0 / AST + 2;

    const size_t bhB = ((size_t)((b * HEADS + h) * 32)) << 13;

    if (tid == 0) {
        MBARRIER_INIT(sb, 1);
#pragma unroll
        for (int s = 0; s < AKV_STAGES; s++) MBARRIER_INIT(sb + 8 + s * 8, 1);
    }
    __syncthreads();

    auto issue_kv = [&](int chunk, int buf) {
        const uint32_t st = sKV + buf * AKV_BUF;
        const uint32_t bar = sb + 8 + buf * 8;
        const size_t src = bhB + (((size_t)chunk) << 13);
        MBAR_EXPECT(bar, AKV_BUF);
        bulk_g2s(st,                (const char*)g_kr + src, AKV_TILE, bar);
        bulk_g2s(st + AKV_TILE,     (const char*)g_ki + src, AKV_TILE, bar);
        bulk_g2s(st + 2 * AKV_TILE, (const char*)g_vv + src, AKV_TILE, bar);
    };

    if (tid == 0) {
        const size_t qsrc = bhB + (((size_t)(q0 >> 6)) << 13);
        MBAR_EXPECT(sb, 2 * AQ_TILE);
        bulk_g2s(sQ,           (const char*)g_qr + qsrc, AQ_TILE, sb);
        bulk_g2s(sQ + AQ_TILE, (const char*)g_qi + qsrc, AQ_TILE, sb);
#pragma unroll
        for (int c = 0; c < AKV_STAGES; c++)
            if (c < nS) issue_kv(c, c);
    }

    const int a_row = lane & 15;
    const uint32_t a_cb = (uint32_t)((lane >> 4) * 16);
    const int b_row = ((lane >> 4) & 1) * 8 + (lane & 7);
    const uint32_t b_cb = (uint32_t)(((lane >> 3) & 1) * 16);

    const int t0g = q0 + w * 16 + (lane >> 2);
    const int t1g = t0g + 8;
    const float2 gt0 = g_gate[h * SEQ + t0g];
    const float2 gt1 = g_gate[h * SEQ + t1g];

    float m0 = -INFINITY, m1 = -INFINITY, l0 = 0.f, l1 = 0.f;
    float oacc[8][4];
#pragma unroll
    for (int f = 0; f < 8; f++)
#pragma unroll
        for (int e = 0; e < 4; e++) oacc[f][e] = 0.f;

    MBARRIER_WAIT_PARITY(sb, 0);

    for (int i = 0; i < nS; i++) {
        const int stg = i % AKV_STAGES;
        MBARRIER_WAIT_PARITY(sb + 8 + stg * 8, (i / AKV_STAGES) & 1);

        const int s0 = i * AST;
        const uint32_t kb0 = sKV + stg * AKV_BUF;
        const uint32_t kR = kb0, kI = kb0 + AKV_TILE, vT = kb0 + 2 * AKV_TILE;

        float sacc[8][4];
#pragma unroll
        for (int f = 0; f < 8; f++)
#pragma unroll
            for (int e = 0; e < 4; e++) sacc[f][e] = 0.f;

#pragma unroll
        for (int jd = 0; jd < 4; jd++) {
            const uint32_t kb = (uint32_t)(jd * 32);
            const uint32_t offA = SWZ128((uint32_t)((w * 16 + a_row) * 128) + kb + a_cb);
            uint32_t aqr[4], aqi[4];
            ldsm_x4(aqr[0], aqr[1], aqr[2], aqr[3], sQ + offA);
            ldsm_x4(aqi[0], aqi[1], aqi[2], aqi[3], sQ + AQ_TILE + offA);
#pragma unroll
            for (int gp = 0; gp < 2; gp++) {
                uint32_t rf[2][4], imf[2][4];
#pragma unroll
                for (int g2 = 0; g2 < 2; g2++) {
                    const int g = gp * 2 + g2;
                    const uint32_t offB = SWZ128((uint32_t)((g * 16 + b_row) * 128) + kb + b_cb);
                    ldsm_x4(rf[g2][0], rf[g2][1], rf[g2][2], rf[g2][3], kR + offB);
                    ldsm_x4(imf[g2][0], imf[g2][1], imf[g2][2], imf[g2][3], kI + offB);
                }
                // pass 1: qr x kr (4 independent MMAs)
#pragma unroll
                for (int g2 = 0; g2 < 2; g2++) {
                    const int s2 = 2 * (gp * 2 + g2);
                    mma_fp16(sacc[s2],     aqr, rf[g2][0], rf[g2][1]);
                    mma_fp16(sacc[s2 + 1], aqr, rf[g2][2], rf[g2][3]);
                }
                // pass 2: qi x ki
#pragma unroll
                for (int g2 = 0; g2 < 2; g2++) {
                    const int s2 = 2 * (gp * 2 + g2);
                    mma_fp16(sacc[s2],     aqi, imf[g2][0], imf[g2][1]);
                    mma_fp16(sacc[s2 + 1], aqi, imf[g2][2], imf[g2][3]);
                }
            }
        }

        float pm0 = -INFINITY, pm1 = -INFINITY;
#pragma unroll
        for (int f = 0; f < 8; f++) {
            const int sb2 = s0 + f * 8 + (lane & 3) * 2;
            const float2 gs0 = g_gate[h * SEQ + sb2];
            const float2 gs1 = g_gate[h * SEQ + sb2 + 1];
            float v00 = sacc[f][0] * SCALE_F * (gs0.x * gt0.x + gs0.y * gt0.y);
            float v01 = sacc[f][1] * SCALE_F * (gs1.x * gt0.x + gs1.y * gt0.y);
            float v10 = sacc[f][2] * SCALE_F * (gs0.x * gt1.x + gs0.y * gt1.y);
            float v11 = sacc[f][3] * SCALE_F * (gs1.x * gt1.x + gs1.y * gt1.y);
            if (sb2 > t0g)     v00 = -INFINITY;
            if (sb2 + 1 > t0g) v01 = -INFINITY;
            if (sb2 > t1g)     v10 = -INFINITY;
            if (sb2 + 1 > t1g) v11 = -INFINITY;
            sacc[f][0] = v00; sacc[f][1] = v01; sacc[f][2] = v10; sacc[f][3] = v11;
            pm0 = fmaxf(pm0, fmaxf(v00, v01));
            pm1 = fmaxf(pm1, fmaxf(v10, v11));
        }
        pm0 = fmaxf(pm0, __shfl_xor_sync(0xffffffffu, pm0, 1));
        pm0 = fmaxf(pm0, __shfl_xor_sync(0xffffffffu, pm0, 2));
        pm1 = fmaxf(pm1, __shfl_xor_sync(0xffffffffu, pm1, 1));
        pm1 = fmaxf(pm1, __shfl_xor_sync(0xffffffffu, pm1, 2));

        const float mn0 = fmaxf(m0, pm0), mn1 = fmaxf(m1, pm1);
        const float cr0 = __expf(m0 - mn0), cr1 = __expf(m1 - mn1);
        float rs0 = 0.f, rs1 = 0.f;
#pragma unroll
        for (int f = 0; f < 8; f++) {
            sacc[f][0] = __expf(sacc[f][0] - mn0);
            sacc[f][1] = __expf(sacc[f][1] - mn0);
            sacc[f][2] = __expf(sacc[f][2] - mn1);
            sacc[f][3] = __expf(sacc[f][3] - mn1);
            rs0 += sacc[f][0] + sacc[f][1];
            rs1 += sacc[f][2] + sacc[f][3];
        }
        rs0 += __shfl_xor_sync(0xffffffffu, rs0, 1);
        rs0 += __shfl_xor_sync(0xffffffffu, rs0, 2);
        rs1 += __shfl_xor_sync(0xffffffffu, rs1, 1);
        rs1 += __shfl_xor_sync(0xffffffffu, rs1, 2);
        l0 = l0 * cr0 + rs0; m0 = mn0;
        l1 = l1 * cr1 + rs1; m1 = mn1;
#pragma unroll
        for (int f = 0; f < 8; f++) {
            oacc[f][0] *= cr0; oacc[f][1] *= cr0;
            oacc[f][2] *= cr1; oacc[f][3] *= cr1;
        }

#pragma unroll
        for (int j = 0; j < 4; j++) {
            uint32_t ph[4] = {
                pack_half(sacc[2 * j][0],     sacc[2 * j][1]),
                pack_half(sacc[2 * j][2],     sacc[2 * j][3]),
                pack_half(sacc[2 * j + 1][0], sacc[2 * j + 1][1]),
                pack_half(sacc[2 * j + 1][2], sacc[2 * j + 1][3])};
#pragma unroll
            for (int dgp = 0; dgp < 2; dgp++) {
                uint32_t vf[2][4];
#pragma unroll
                for (int d2 = 0; d2 < 2; d2++) {
                    const int dg = dgp * 2 + d2;
                    const uint32_t offV = SWZ128((uint32_t)((16 * j + a_row) * 128) +
                                                 (uint32_t)(dg * 32) + a_cb);
                    ldsm_x4_t(vf[d2][0], vf[d2][1], vf[d2][2], vf[d2][3], vT + offV);
                }
                // 1 pass x 4 independent MMAs
#pragma unroll
                for (int d2 = 0; d2 < 2; d2++) {
                    const int o2 = 2 * (dgp * 2 + d2);
                    mma_fp16(oacc[o2],     ph, vf[d2][0], vf[d2][1]);
                    mma_fp16(oacc[o2 + 1], ph, vf[d2][2], vf[d2][3]);
                }
            }
        }
        __syncthreads();
        if (i + AKV_STAGES < nS && tid == 0) issue_kv(i + AKV_STAGES, stg);
    }

    // epilogue: normalize, write fp16 hi/lo in GEMM-A tiled layout
    const float iv0 = 1.0f / l0, iv1 = 1.0f / l1;
#pragma unroll
    for (int f = 0; f < 8; f++) {
        const int d = f * 8 + (lane & 3) * 2;
        float o00 = oacc[f][0] * iv0, o01 = oacc[f][1] * iv0;
        float o10 = oacc[f][2] * iv1, o11 = oacc[f][3] * iv1;
        float h00 = __half2float(__float2half(o00));
        float h01 = __half2float(__float2half(o01));
        float h10 = __half2float(__float2half(o10));
        float h11 = __half2float(__float2half(o11));
        size_t off0 = gemmA_off(b * SEQ + t0g, h * 64 + d);
        size_t off1 = gemmA_off(b * SEQ + t1g, h * 64 + d);
        *(uint32_t*)((char*)g_ah + off0) = pack_half(h00, h01);
        *(uint32_t*)((char*)g_al + off0) = pack_half(o00 - h00, o01 - h01);
        *(uint32_t*)((char*)g_ah + off1) = pack_half(h10, h11);
        *(uint32_t*)((char*)g_al + off1) = pack_half(o10 - h10, o11 - h11);
    }
}

// ---------------- launch ---------------------------------------------------
extern "C" void kernel_launch(void* const* d_in, const int* in_sizes, int n_in,
                              void* d_out, int out_size) {
    const float* x     = (const float*)d_in[0];
    const float* Wq    = (const float*)d_in[1];
    const float* Wk    = (const float*)d_in[2];
    const float* Wv    = (const float*)d_in[3];
    const float* Wo    = (const float*)d_in[4];
    const float* theta = (const float*)d_in[5];
    float* out = (float*)d_out;

    float *qraw, *kraw, *v;
    __half *xh, *xl, *ah, *al, *vv, *wq, *wk, *wv, *wo;
    cudaGetSymbolAddress((void**)&qraw, g_qraw);
    cudaGetSymbolAddress((void**)&kraw, g_kraw);
    cudaGetSymbolAddress((void**)&v,    g_v);
    cudaGetSymbolAddress((void**)&xh,  g_xh);
    cudaGetSymbolAddress((void**)&xl,  g_xl);
    cudaGetSymbolAddress((void**)&ah,  g_ah);
    cudaGetSymbolAddress((void**)&al,  g_al);
    cudaGetSymbolAddress((void**)&vv,  g_vv);
    cudaGetSymbolAddress((void**)&wq,  g_wq);
    cudaGetSymbolAddress((void**)&wk,  g_wk);
    cudaGetSymbolAddress((void**)&wv,  g_wv);
    cudaGetSymbolAddress((void**)&wo,  g_wo);

    cudaFuncSetAttribute(gemm_qkv,
                         cudaFuncAttributeMaxDynamicSharedMemorySize, GEMM_SMEM);
    cudaFuncSetAttribute(gemm_out,
                         cudaFuncAttributeMaxDynamicSharedMemorySize, GEMM_SMEM);
    cudaFuncSetAttribute(attn_mma,
                         cudaFuncAttributeMaxDynamicSharedMemorySize, ATT_SMEM);

    dim3 tblk(32, 8);

    convert_split_gemm<<<MROWS * CDIM / 2 / 256, 256>>>(x, xh, xl);
    gate_init<<<HEADS * SEQ / 256, 256>>>(theta);
    transpose_half<<<dim3(2 * CDIM / 32, CDIM / 32), tblk>>>(Wq, wq, CDIM, 2 * CDIM);
    transpose_half<<<dim3(2 * CDIM / 32, CDIM / 32), tblk>>>(Wk, wk, CDIM, 2 * CDIM);
    transpose_half<<<dim3(CDIM / 32, CDIM / 32), tblk>>>(Wv, wv, CDIM, CDIM);
    transpose_half<<<dim3(CDIM / 32, CDIM / 32), tblk>>>(Wo, wo, CDIM, CDIM);

    gemm_qkv<<<dim3(20, MROWS / 128), 256, GEMM_SMEM>>>(
        xh, xl, wq, wk, wv, qraw, kraw, v);

    transform_qk_fp16<<<MROWS * CDIM / 2 / 256, 256>>>();
    convert_att_single<<<MROWS * CDIM / 2 / 256, 256>>>(v, vv);

    attn_mma<<<dim3(SEQ / AQT, HEADS, BATCH), 256, ATT_SMEM>>>();

    gemm_out<<<dim3(CDIM / 256, MROWS / 128), 256, GEMM_SMEM>>>(ah, al, wo, out, CDIM);
}